// round 12
// baseline (speedup 1.0000x reference)
#include <cuda_runtime.h>
#include <cuda_fp16.h>
#include <math_constants.h>

// ---------------------------------------------------------------------------
// GAT 2-layer forward, fixed shapes. CSR-based, zero float atomics.
// R10: fp16 shadow copies for aggregation gathers (halves L2 gather bytes),
//      block-partitioned fusion (gemm1||prep, att1||scan1), deg re-zeroed by
//      k_l2 tail blocks (invariant across graph replays).
// ---------------------------------------------------------------------------

#define NNODES 100000
#define E_IN   1600000
#define ETOT   (E_IN + NNODES)
#define NH1    4
#define F1     128
#define FIN    256
#define CO     64
#define EPSV   1e-16f
#define SCAN_B 512
#define NB1    ((NNODES + SCAN_B - 1) / SCAN_B)   // 196

static const int TPB = 256;

// ---------------- device scratch (static, 16B-aligned) ----------------------
__device__ __align__(16) float  g_h1  [(size_t)NNODES * F1];
__device__ __align__(16) __half g_h1h [(size_t)NNODES * F1];
__device__ __align__(16) float  g_agg1[(size_t)NNODES * F1];
__device__ __align__(16) float  g_h2  [(size_t)NNODES * CO];
__device__ __align__(16) __half g_h2h [(size_t)NNODES * CO];
__device__ __align__(16) float  g_asrc1[NNODES * NH1];
__device__ __align__(16) float  g_adst1[NNODES * NH1];
__device__ __align__(16) float  g_ex1 [(size_t)ETOT * NH1];   // deg>64 fallback
__device__ __align__(16) float  g_asrc2[NNODES];
__device__ __align__(16) float  g_adst2[NNODES];
__device__ __align__(16) float  g_ex2 [ETOT];                 // deg>64 fallback
// CSR machinery (g_deg zero-initialized statically; re-zeroed by k_l2 tail)
__device__ int g_esrc[ETOT];
__device__ int g_edst[ETOT];
__device__ int g_csrc[ETOT];
__device__ int g_deg [NNODES];
__device__ int g_scan[NNODES];
__device__ int g_boff[NB1 + 32];
__device__ int g_rowptr[NNODES + 1];
__device__ int g_wcur[NNODES];

// ---------------- helpers ----------------------------------------------------
__device__ __forceinline__ float lrelu(float v) { return v >= 0.f ? v : 0.2f * v; }
__device__ __forceinline__ float4 lrelu4(float4 v) {
    return make_float4(lrelu(v.x), lrelu(v.y), lrelu(v.z), lrelu(v.w));
}
__device__ __forceinline__ float4 max4(float4 a, float4 b) {
    return make_float4(fmaxf(a.x, b.x), fmaxf(a.y, b.y),
                       fmaxf(a.z, b.z), fmaxf(a.w, b.w));
}
__device__ __forceinline__ float4 exp4(float4 a, float4 m) {
    return make_float4(__expf(a.x - m.x), __expf(a.y - m.y),
                       __expf(a.z - m.z), __expf(a.w - m.w));
}
__device__ __forceinline__ float4 wred_max4(float4 v) {
#pragma unroll
    for (int o = 16; o > 0; o >>= 1) {
        v.x = fmaxf(v.x, __shfl_xor_sync(0xffffffffu, v.x, o));
        v.y = fmaxf(v.y, __shfl_xor_sync(0xffffffffu, v.y, o));
        v.z = fmaxf(v.z, __shfl_xor_sync(0xffffffffu, v.z, o));
        v.w = fmaxf(v.w, __shfl_xor_sync(0xffffffffu, v.w, o));
    }
    return v;
}
__device__ __forceinline__ float4 wred_sum4(float4 v) {
#pragma unroll
    for (int o = 16; o > 0; o >>= 1) {
        v.x += __shfl_xor_sync(0xffffffffu, v.x, o);
        v.y += __shfl_xor_sync(0xffffffffu, v.y, o);
        v.z += __shfl_xor_sync(0xffffffffu, v.z, o);
        v.w += __shfl_xor_sync(0xffffffffu, v.w, o);
    }
    return v;
}
__device__ __forceinline__ unsigned f2tf32(float f) {
    unsigned u;
    asm("cvt.rna.tf32.f32 %0, %1;" : "=r"(u) : "f"(f));
    return u;
}
__device__ __forceinline__ void mma_tf32(float4& d, const unsigned a[4],
                                         unsigned b0, unsigned b1) {
    asm volatile(
        "mma.sync.aligned.m16n8k8.row.col.f32.tf32.tf32.f32 "
        "{%0,%1,%2,%3}, {%4,%5,%6,%7}, {%8,%9}, {%0,%1,%2,%3};\n"
        : "+f"(d.x), "+f"(d.y), "+f"(d.z), "+f"(d.w)
        : "r"(a[0]), "r"(a[1]), "r"(a[2]), "r"(a[3]), "r"(b0), "r"(b1));
}

// ---------------- fused: gemm1 (tf32 HMMA) || edge prep ----------------------
#define GB1 ((NNODES + 127) / 128)          // 782 gemm blocks
#define PB  ((ETOT + 255) / 256)            // 6641 prep blocks

__global__ void __launch_bounds__(256) k_gemm1_prep(const float* __restrict__ A,
                                                    const float* __restrict__ B,
                                                    const void* __restrict__ ei_raw) {
    __shared__ unsigned As[128][36];
    __shared__ unsigned Bs[32][136];

    if (blockIdx.x >= GB1) {
        // ---- edge prep: dtype-robust decode + degree histogram ----
        int e = (blockIdx.x - GB1) * 256 + threadIdx.x;
        if (e >= ETOT) return;
        int s, d;
        if (e >= E_IN) {
            s = d = e - E_IN;
        } else {
            const long long* e64 = (const long long*)ei_raw;
            bool is64 = true;
#pragma unroll
            for (int q = 0; q < 4; q++) {
                long long v = e64[q];
                if (v < 0 || v >= NNODES) is64 = false;
            }
            if (is64) {
                s = (int)e64[e];
                d = (int)e64[(size_t)E_IN + e];
            } else {
                const int* e32 = (const int*)ei_raw;
                s = e32[e];
                d = e32[E_IN + e];
            }
        }
        g_esrc[e] = s;
        g_edst[e] = d;
        atomicAdd(&g_deg[d], 1);
        return;
    }

    // ---- gemm1: 128x128 tile, BK=32, 8 warps, warp tile 32x64 ----
    const int tid  = threadIdx.x;
    const int lane = tid & 31, wid = tid >> 5;
    const int wm = (wid & 3) * 32;
    const int wn = (wid >> 2) * 64;
    const int row0 = blockIdx.x * 128;
    const int g = lane >> 2, tg = lane & 3;

    float4 acc[2][8];
#pragma unroll
    for (int mt = 0; mt < 2; mt++)
#pragma unroll
        for (int nt = 0; nt < 8; nt++) acc[mt][nt] = make_float4(0, 0, 0, 0);

    for (int k0 = 0; k0 < FIN; k0 += 32) {
#pragma unroll
        for (int q = 0; q < 4; q++) {
            int f4 = tid + q * 256;
            int r = f4 >> 3, c = (f4 & 7) * 4;
            float4 v = make_float4(0, 0, 0, 0);
            int gr = row0 + r;
            if (gr < NNODES) v = *(const float4*)&A[(size_t)gr * FIN + k0 + c];
            *(uint4*)&As[r][c] =
                make_uint4(f2tf32(v.x), f2tf32(v.y), f2tf32(v.z), f2tf32(v.w));
        }
#pragma unroll
        for (int q = 0; q < 4; q++) {
            int f4 = tid + q * 256;
            int r = f4 >> 5, c = (f4 & 31) * 4;
            float4 v = *(const float4*)&B[(size_t)(k0 + r) * F1 + c];
            *(uint4*)&Bs[r][c] =
                make_uint4(f2tf32(v.x), f2tf32(v.y), f2tf32(v.z), f2tf32(v.w));
        }
        __syncthreads();

#pragma unroll
        for (int kk = 0; kk < 32; kk += 8) {
            unsigned a[2][4];
#pragma unroll
            for (int mt = 0; mt < 2; mt++) {
                int rb = wm + mt * 16;
                a[mt][0] = As[rb + g][kk + tg];
                a[mt][1] = As[rb + 8 + g][kk + tg];
                a[mt][2] = As[rb + g][kk + tg + 4];
                a[mt][3] = As[rb + 8 + g][kk + tg + 4];
            }
#pragma unroll
            for (int nt = 0; nt < 8; nt++) {
                unsigned b0 = Bs[kk + tg][wn + nt * 8 + g];
                unsigned b1 = Bs[kk + 4 + tg][wn + nt * 8 + g];
                mma_tf32(acc[0][nt], a[0], b0, b1);
                mma_tf32(acc[1][nt], a[1], b0, b1);
            }
        }
        __syncthreads();
    }

#pragma unroll
    for (int mt = 0; mt < 2; mt++) {
#pragma unroll
        for (int nt = 0; nt < 8; nt++) {
            int r = row0 + wm + mt * 16 + g;
            int c = wn + nt * 8 + tg * 2;
            if (r < NNODES) {
                *(float2*)&g_h1[(size_t)r * F1 + c] =
                    make_float2(acc[mt][nt].x, acc[mt][nt].y);
                *(__half2*)&g_h1h[(size_t)r * F1 + c] =
                    __floats2half2_rn(acc[mt][nt].x, acc[mt][nt].y);
            }
            if (r + 8 < NNODES) {
                *(float2*)&g_h1[(size_t)(r + 8) * F1 + c] =
                    make_float2(acc[mt][nt].z, acc[mt][nt].w);
                *(__half2*)&g_h1h[(size_t)(r + 8) * F1 + c] =
                    __floats2half2_rn(acc[mt][nt].z, acc[mt][nt].w);
            }
        }
    }
}

// ---------------- fused: att1 || scan1 (512-thread blocks) --------------------
#define AB1 ((NNODES * NH1 + 511) / 512)    // 782 att1 blocks

__global__ void __launch_bounds__(512) k_att1_scan1(const float* __restrict__ att_s,
                                                    const float* __restrict__ att_d) {
    if (blockIdx.x < AB1) {
        __shared__ float ss[F1], sd[F1];
        if (threadIdx.x < F1) { ss[threadIdx.x] = att_s[threadIdx.x];
                                sd[threadIdx.x] = att_d[threadIdx.x]; }
        __syncthreads();
        int i = blockIdx.x * 512 + threadIdx.x;
        if (i >= NNODES * NH1) return;
        int n = i >> 2, h = i & 3;
        const float4* hv = (const float4*)&g_h1[(size_t)n * F1 + h * 32];
        const float4* sv = (const float4*)&ss[h * 32];
        const float4* dv = (const float4*)&sd[h * 32];
        float s = 0.f, d = 0.f;
#pragma unroll
        for (int q = 0; q < 8; q++) {
            float4 hh = hv[q], a = sv[q], b = dv[q];
            s += hh.x * a.x + hh.y * a.y + hh.z * a.z + hh.w * a.w;
            d += hh.x * b.x + hh.y * b.y + hh.z * b.z + hh.w * b.w;
        }
        g_asrc1[i] = s;
        g_adst1[i] = d;
        return;
    }

    // ---- scan1: per-block inclusive scan of degrees ----
    int t = threadIdx.x, b = blockIdx.x - AB1;
    int i = b * SCAN_B + t;
    int val = (i < NNODES) ? g_deg[i] : 0;
    int lane = t & 31, wid = t >> 5;
    int v = val;
#pragma unroll
    for (int o = 1; o < 32; o <<= 1) {
        int u = __shfl_up_sync(0xffffffffu, v, o);
        if (lane >= o) v += u;
    }
    __shared__ int wsum[SCAN_B / 32];
    if (lane == 31) wsum[wid] = v;
    __syncthreads();
    if (wid == 0) {
        int w = (lane < SCAN_B / 32) ? wsum[lane] : 0;
#pragma unroll
        for (int o = 1; o < 32; o <<= 1) {
            int u = __shfl_up_sync(0xffffffffu, w, o);
            if (lane >= o) w += u;
        }
        if (lane < SCAN_B / 32) wsum[lane] = w;
    }
    __syncthreads();
    int incl = v + (wid ? wsum[wid - 1] : 0);
    if (i < NNODES) g_scan[i] = incl;
    if (t == SCAN_B - 1) g_boff[b] = incl;
}

// ---------------- scan phases 2,3 + scatter ------------------------------------
__global__ void k_scan2() {
    int t = threadIdx.x;
    int val = (t < NB1) ? g_boff[t] : 0;
    int lane = t & 31, wid = t >> 5;
    int v = val;
#pragma unroll
    for (int o = 1; o < 32; o <<= 1) {
        int u = __shfl_up_sync(0xffffffffu, v, o);
        if (lane >= o) v += u;
    }
    __shared__ int wsum[8];
    if (lane == 31) wsum[wid] = v;
    __syncthreads();
    if (wid == 0) {
        int w = (lane < 8) ? wsum[lane] : 0;
#pragma unroll
        for (int o = 1; o < 8; o <<= 1) {
            int u = __shfl_up_sync(0xffffffffu, w, o);
            if (lane >= o) w += u;
        }
        if (lane < 8) wsum[lane] = w;
    }
    __syncthreads();
    int incl = v + (wid ? wsum[wid - 1] : 0);
    if (t < NB1) g_boff[t] = incl - val;
}
__global__ void k_scan3() {
    int i = blockIdx.x * blockDim.x + threadIdx.x;
    if (i >= NNODES) return;
    int base = g_boff[i / SCAN_B];
    int excl = base + g_scan[i] - g_deg[i];
    g_rowptr[i] = excl;
    g_wcur[i]   = excl;
    if (i == 0) g_rowptr[NNODES] = ETOT;
}
__global__ void k_scatter() {
    int e = blockIdx.x * blockDim.x + threadIdx.x;
    if (e >= ETOT) return;
    int d = g_edst[e];
    int pos = atomicAdd(&g_wcur[d], 1);
    g_csrc[pos] = g_esrc[e];
}

// ---------------- gemm2: g_h2 = g_agg1 @ W2, tf32 HMMA + fp16 shadow ----------
__global__ void __launch_bounds__(256) gemm2_kernel(const float* __restrict__ B) {
    __shared__ unsigned As[128][36];
    __shared__ unsigned Bs[32][72];
    const float* A = g_agg1;
    const int tid  = threadIdx.x;
    const int lane = tid & 31, wid = tid >> 5;
    const int wm = (wid & 3) * 32;
    const int wn = (wid >> 2) * 32;
    const int row0 = blockIdx.x * 128;
    const int g = lane >> 2, tg = lane & 3;

    float4 acc[2][4];
#pragma unroll
    for (int mt = 0; mt < 2; mt++)
#pragma unroll
        for (int nt = 0; nt < 4; nt++) acc[mt][nt] = make_float4(0, 0, 0, 0);

    for (int k0 = 0; k0 < F1; k0 += 32) {
#pragma unroll
        for (int q = 0; q < 4; q++) {
            int f4 = tid + q * 256;
            int r = f4 >> 3, c = (f4 & 7) * 4;
            float4 v = make_float4(0, 0, 0, 0);
            int gr = row0 + r;
            if (gr < NNODES) v = *(const float4*)&A[(size_t)gr * F1 + k0 + c];
            *(uint4*)&As[r][c] =
                make_uint4(f2tf32(v.x), f2tf32(v.y), f2tf32(v.z), f2tf32(v.w));
        }
#pragma unroll
        for (int q = 0; q < 2; q++) {
            int f4 = tid + q * 256;
            int r = f4 >> 4, c = (f4 & 15) * 4;
            float4 v = *(const float4*)&B[(size_t)(k0 + r) * CO + c];
            *(uint4*)&Bs[r][c] =
                make_uint4(f2tf32(v.x), f2tf32(v.y), f2tf32(v.z), f2tf32(v.w));
        }
        __syncthreads();

#pragma unroll
        for (int kk = 0; kk < 32; kk += 8) {
            unsigned a[2][4];
#pragma unroll
            for (int mt = 0; mt < 2; mt++) {
                int rb = wm + mt * 16;
                a[mt][0] = As[rb + g][kk + tg];
                a[mt][1] = As[rb + 8 + g][kk + tg];
                a[mt][2] = As[rb + g][kk + tg + 4];
                a[mt][3] = As[rb + 8 + g][kk + tg + 4];
            }
#pragma unroll
            for (int nt = 0; nt < 4; nt++) {
                unsigned b0 = Bs[kk + tg][wn + nt * 8 + g];
                unsigned b1 = Bs[kk + 4 + tg][wn + nt * 8 + g];
                mma_tf32(acc[0][nt], a[0], b0, b1);
                mma_tf32(acc[1][nt], a[1], b0, b1);
            }
        }
        __syncthreads();
    }

#pragma unroll
    for (int mt = 0; mt < 2; mt++) {
#pragma unroll
        for (int nt = 0; nt < 4; nt++) {
            int r = row0 + wm + mt * 16 + g;
            int c = wn + nt * 8 + tg * 2;
            if (r < NNODES) {
                *(float2*)&g_h2[(size_t)r * CO + c] =
                    make_float2(acc[mt][nt].x, acc[mt][nt].y);
                *(__half2*)&g_h2h[(size_t)r * CO + c] =
                    __floats2half2_rn(acc[mt][nt].x, acc[mt][nt].y);
            }
            if (r + 8 < NNODES) {
                *(float2*)&g_h2[(size_t)(r + 8) * CO + c] =
                    make_float2(acc[mt][nt].z, acc[mt][nt].w);
                *(__half2*)&g_h2h[(size_t)(r + 8) * CO + c] =
                    __floats2half2_rn(acc[mt][nt].z, acc[mt][nt].w);
            }
        }
    }
}

// ---------------- att2 ---------------------------------------------------------
__global__ void k_att2(const float* __restrict__ att_s,
                       const float* __restrict__ att_d) {
    __shared__ float ss[CO], sd[CO];
    if (threadIdx.x < CO) { ss[threadIdx.x] = att_s[threadIdx.x];
                            sd[threadIdx.x] = att_d[threadIdx.x]; }
    __syncthreads();
    int n = blockIdx.x * blockDim.x + threadIdx.x;
    if (n >= NNODES) return;
    const float4* hv = (const float4*)&g_h2[(size_t)n * CO];
    const float4* sv = (const float4*)ss;
    const float4* dv = (const float4*)sd;
    float s = 0.f, d = 0.f;
#pragma unroll
    for (int q = 0; q < CO / 4; q++) {
        float4 hh = hv[q], a = sv[q], b = dv[q];
        s += hh.x * a.x + hh.y * a.y + hh.z * a.z + hh.w * a.w;
        d += hh.x * b.x + hh.y * b.y + hh.z * b.z + hh.w * b.w;
    }
    g_asrc2[n] = s;
    g_adst2[n] = d;
}

// ---------------- layer-1: fused softmax+aggregate (fp16 gathers) -------------
__global__ void __launch_bounds__(256) k_l1(const float* __restrict__ b1) {
    __shared__ float4 sal[8][64];
    int w = (blockIdx.x * blockDim.x + threadIdx.x) >> 5;
    if (w >= NNODES) return;
    const int n = w, lane = threadIdx.x & 31, ws = (threadIdx.x >> 5);
    const int beg = g_rowptr[n], end = g_rowptr[n + 1];
    const int deg = end - beg;
    const float4 ad = *(const float4*)&g_adst1[n * 4];
    const int h = lane >> 3;
    float4 acc = make_float4(0, 0, 0, 0);

    if (deg <= 64) {
        int s0 = 0, s1 = 0;
        float4 e0 = make_float4(0, 0, 0, 0), e1 = e0;
        const int p0 = beg + lane, p1 = p0 + 32;
        const bool v0 = p0 < end, v1 = p1 < end;
        float4 mx = make_float4(-CUDART_INF_F, -CUDART_INF_F,
                                -CUDART_INF_F, -CUDART_INF_F);
        if (v0) {
            s0 = g_csrc[p0];
            e0 = lrelu4(make_float4(g_asrc1[s0 * 4 + 0] + ad.x,
                                    g_asrc1[s0 * 4 + 1] + ad.y,
                                    g_asrc1[s0 * 4 + 2] + ad.z,
                                    g_asrc1[s0 * 4 + 3] + ad.w));
            mx = max4(mx, e0);
        }
        if (v1) {
            s1 = g_csrc[p1];
            e1 = lrelu4(make_float4(g_asrc1[s1 * 4 + 0] + ad.x,
                                    g_asrc1[s1 * 4 + 1] + ad.y,
                                    g_asrc1[s1 * 4 + 2] + ad.z,
                                    g_asrc1[s1 * 4 + 3] + ad.w));
            mx = max4(mx, e1);
        }
        mx = wred_max4(mx);
        float4 sm = make_float4(0, 0, 0, 0);
        float4 x0 = make_float4(0, 0, 0, 0), x1 = x0;
        if (v0) { x0 = exp4(e0, mx); sm.x += x0.x; sm.y += x0.y; sm.z += x0.z; sm.w += x0.w; }
        if (v1) { x1 = exp4(e1, mx); sm.x += x1.x; sm.y += x1.y; sm.z += x1.z; sm.w += x1.w; }
        sm = wred_sum4(sm);
        float4 inv = make_float4(1.f / (sm.x + EPSV), 1.f / (sm.y + EPSV),
                                 1.f / (sm.z + EPSV), 1.f / (sm.w + EPSV));
        if (v0) sal[ws][lane] = make_float4(x0.x * inv.x, x0.y * inv.y,
                                            x0.z * inv.z, x0.w * inv.w);
        if (v1) sal[ws][lane + 32] = make_float4(x1.x * inv.x, x1.y * inv.y,
                                                 x1.z * inv.z, x1.w * inv.w);
        __syncwarp();
        for (int j = 0; j < deg; j++) {
            int sv = (j < 32) ? s0 : s1;
            int s = __shfl_sync(0xffffffffu, sv, j & 31);
            float alpha = ((const float*)&sal[ws][j])[h];
            const __half2* hp = (const __half2*)&g_h1h[(size_t)s * F1 + lane * 4];
            float2 f0 = __half22float2(hp[0]);
            float2 f1 = __half22float2(hp[1]);
            acc.x = fmaf(f0.x, alpha, acc.x);
            acc.y = fmaf(f0.y, alpha, acc.y);
            acc.z = fmaf(f1.x, alpha, acc.z);
            acc.w = fmaf(f1.y, alpha, acc.w);
        }
    } else {
        float4 mx = make_float4(-CUDART_INF_F, -CUDART_INF_F,
                                -CUDART_INF_F, -CUDART_INF_F);
        for (int p = beg + lane; p < end; p += 32) {
            int s = g_csrc[p];
            float4 e = lrelu4(make_float4(g_asrc1[s * 4 + 0] + ad.x,
                                          g_asrc1[s * 4 + 1] + ad.y,
                                          g_asrc1[s * 4 + 2] + ad.z,
                                          g_asrc1[s * 4 + 3] + ad.w));
            *(float4*)&g_ex1[(size_t)p * 4] = e;
            mx = max4(mx, e);
        }
        mx = wred_max4(mx);
        float4 sm = make_float4(0, 0, 0, 0);
        for (int p = beg + lane; p < end; p += 32) {
            float4 e = *(const float4*)&g_ex1[(size_t)p * 4];
            float4 ex = exp4(e, mx);
            *(float4*)&g_ex1[(size_t)p * 4] = ex;
            sm.x += ex.x; sm.y += ex.y; sm.z += ex.z; sm.w += ex.w;
        }
        sm = wred_sum4(sm);
        float4 inv = make_float4(1.f / (sm.x + EPSV), 1.f / (sm.y + EPSV),
                                 1.f / (sm.z + EPSV), 1.f / (sm.w + EPSV));
        __syncwarp();
        const float invh = (h == 0) ? inv.x : (h == 1) ? inv.y
                         : (h == 2) ? inv.z : inv.w;
        for (int p = beg; p < end; ++p) {
            int s = g_csrc[p];
            float alpha = g_ex1[(size_t)p * 4 + h] * invh;
            const __half2* hp = (const __half2*)&g_h1h[(size_t)s * F1 + lane * 4];
            float2 f0 = __half22float2(hp[0]);
            float2 f1 = __half22float2(hp[1]);
            acc.x = fmaf(f0.x, alpha, acc.x);
            acc.y = fmaf(f0.y, alpha, acc.y);
            acc.z = fmaf(f1.x, alpha, acc.z);
            acc.w = fmaf(f1.y, alpha, acc.w);
        }
    }

    float4 b = *(const float4*)&b1[lane * 4];
    float4 v = make_float4(acc.x + b.x, acc.y + b.y, acc.z + b.z, acc.w + b.w);
    v.x = v.x > 0.f ? v.x : expm1f(v.x);
    v.y = v.y > 0.f ? v.y : expm1f(v.y);
    v.z = v.z > 0.f ? v.z : expm1f(v.z);
    v.w = v.w > 0.f ? v.w : expm1f(v.w);
    *(float4*)&g_agg1[(size_t)n * F1 + lane * 4] = v;
}

// ---------------- layer-2: fused softmax+aggregate (fp16) + deg re-zero -------
#define GW2 ((NNODES * 32 + 255) / 256)     // 12500 main blocks
#define ZB2 ((NNODES + 255) / 256)          // 391 zeroing blocks

__global__ void __launch_bounds__(256) k_l2(const float* __restrict__ b2,
                                            float* __restrict__ out) {
    if (blockIdx.x >= GW2) {
        int i = (blockIdx.x - GW2) * 256 + threadIdx.x;
        if (i < NNODES) g_deg[i] = 0;    // restore invariant for next replay
        return;
    }
    __shared__ float sal[8][64];
    int w = (blockIdx.x * blockDim.x + threadIdx.x) >> 5;
    if (w >= NNODES) return;
    const int n = w, lane = threadIdx.x & 31, ws = (threadIdx.x >> 5);
    const int beg = g_rowptr[n], end = g_rowptr[n + 1];
    const int deg = end - beg;
    const float adn = g_adst2[n];
    float2 acc = make_float2(0, 0);

    if (deg <= 64) {
        int s0 = 0, s1 = 0;
        float e0 = 0.f, e1 = 0.f;
        const int p0 = beg + lane, p1 = p0 + 32;
        const bool v0 = p0 < end, v1 = p1 < end;
        float mx = -CUDART_INF_F;
        if (v0) { s0 = g_csrc[p0]; e0 = lrelu(g_asrc2[s0] + adn); mx = fmaxf(mx, e0); }
        if (v1) { s1 = g_csrc[p1]; e1 = lrelu(g_asrc2[s1] + adn); mx = fmaxf(mx, e1); }
#pragma unroll
        for (int o = 16; o > 0; o >>= 1)
            mx = fmaxf(mx, __shfl_xor_sync(0xffffffffu, mx, o));
        float sm = 0.f, x0 = 0.f, x1 = 0.f;
        if (v0) { x0 = __expf(e0 - mx); sm += x0; }
        if (v1) { x1 = __expf(e1 - mx); sm += x1; }
#pragma unroll
        for (int o = 16; o > 0; o >>= 1) sm += __shfl_xor_sync(0xffffffffu, sm, o);
        float inv = 1.f / (sm + EPSV);
        if (v0) sal[ws][lane]      = x0 * inv;
        if (v1) sal[ws][lane + 32] = x1 * inv;
        __syncwarp();
        for (int j = 0; j < deg; j++) {
            int sv = (j < 32) ? s0 : s1;
            int s = __shfl_sync(0xffffffffu, sv, j & 31);
            float alpha = sal[ws][j];
            float2 hv = __half22float2(
                *(const __half2*)&g_h2h[(size_t)s * CO + lane * 2]);
            acc.x = fmaf(hv.x, alpha, acc.x);
            acc.y = fmaf(hv.y, alpha, acc.y);
        }
    } else {
        float mx = -CUDART_INF_F;
        for (int p = beg + lane; p < end; p += 32) {
            int s = g_csrc[p];
            float e = lrelu(g_asrc2[s] + adn);
            g_ex2[p] = e;
            mx = fmaxf(mx, e);
        }
#pragma unroll
        for (int o = 16; o > 0; o >>= 1)
            mx = fmaxf(mx, __shfl_xor_sync(0xffffffffu, mx, o));
        float sm = 0.f;
        for (int p = beg + lane; p < end; p += 32) {
            float ex = __expf(g_ex2[p] - mx);
            g_ex2[p] = ex;
            sm += ex;
        }
#pragma unroll
        for (int o = 16; o > 0; o >>= 1) sm += __shfl_xor_sync(0xffffffffu, sm, o);
        float inv = 1.f / (sm + EPSV);
        __syncwarp();
        for (int p = beg; p < end; ++p) {
            int s = g_csrc[p];
            float alpha = g_ex2[p] * inv;
            float2 hv = __half22float2(
                *(const __half2*)&g_h2h[(size_t)s * CO + lane * 2]);
            acc.x = fmaf(hv.x, alpha, acc.x);
            acc.y = fmaf(hv.y, alpha, acc.y);
        }
    }

    float2 b = *(const float2*)&b2[lane * 2];
    *(float2*)&out[(size_t)n * CO + lane * 2] = make_float2(acc.x + b.x, acc.y + b.y);
}

// ---------------- launcher -------------------------------------------------------
extern "C" void kernel_launch(void* const* d_in, const int* in_sizes, int n_in,
                              void* d_out, int out_size) {
    const float* x   = (const float*)d_in[0];
    const void*  ei  = d_in[1];
    const float* W1  = (const float*)d_in[2];
    const float* as1 = (const float*)d_in[3];
    const float* ad1 = (const float*)d_in[4];
    const float* b1  = (const float*)d_in[5];
    const float* W2  = (const float*)d_in[6];
    const float* as2 = (const float*)d_in[7];
    const float* ad2 = (const float*)d_in[8];
    const float* b2  = (const float*)d_in[9];
    float* out = (float*)d_out;

    (void)in_sizes; (void)n_in; (void)out_size;

    const int gNode = (NNODES + TPB - 1) / TPB;
    const int gEdge = (ETOT + TPB - 1) / TPB;

    // gemm1 || edge prep (deg is zero: static init on first run, k_l2 tail after)
    k_gemm1_prep<<<GB1 + PB, 256>>>(x, W1, ei);
    // att1 || scan1
    k_att1_scan1<<<AB1 + NB1, SCAN_B>>>(as1, ad1);
    k_scan2<<<1, 256>>>();
    k_scan3<<<gNode, TPB>>>();
    k_scatter<<<gEdge, TPB>>>();

    k_l1<<<GW2, TPB>>>(b1);

    gemm2_kernel<<<(NNODES + 127) / 128, 256>>>(W2);
    k_att2<<<gNode, TPB>>>(as2, ad2);
    k_l2<<<GW2 + ZB2, TPB>>>(b2, out);
}

// round 13
// speedup vs baseline: 1.0058x; 1.0058x over previous
#include <cuda_runtime.h>
#include <cuda_fp16.h>
#include <math_constants.h>

// ---------------------------------------------------------------------------
// GAT 2-layer forward, fixed shapes. CSR-based, zero float atomics.
// R10: fp16 shadow copies for aggregation gathers (halves L2 gather bytes),
//      block-partitioned fusion (gemm1||prep, att1||scan1), deg re-zeroed by
//      k_l2 tail blocks (invariant across graph replays).
// ---------------------------------------------------------------------------

#define NNODES 100000
#define E_IN   1600000
#define ETOT   (E_IN + NNODES)
#define NH1    4
#define F1     128
#define FIN    256
#define CO     64
#define EPSV   1e-16f
#define SCAN_B 512
#define NB1    ((NNODES + SCAN_B - 1) / SCAN_B)   // 196

static const int TPB = 256;

// ---------------- device scratch (static, 16B-aligned) ----------------------
__device__ __align__(16) float  g_h1  [(size_t)NNODES * F1];
__device__ __align__(16) __half g_h1h [(size_t)NNODES * F1];
__device__ __align__(16) float  g_agg1[(size_t)NNODES * F1];
__device__ __align__(16) float  g_h2  [(size_t)NNODES * CO];
__device__ __align__(16) __half g_h2h [(size_t)NNODES * CO];
__device__ __align__(16) float  g_asrc1[NNODES * NH1];
__device__ __align__(16) float  g_adst1[NNODES * NH1];
__device__ __align__(16) float  g_ex1 [(size_t)ETOT * NH1];   // deg>64 fallback
__device__ __align__(16) float  g_asrc2[NNODES];
__device__ __align__(16) float  g_adst2[NNODES];
__device__ __align__(16) float  g_ex2 [ETOT];                 // deg>64 fallback
// CSR machinery (g_deg zero-initialized statically; re-zeroed by k_l2 tail)
__device__ int g_esrc[ETOT];
__device__ int g_edst[ETOT];
__device__ int g_csrc[ETOT];
__device__ int g_deg [NNODES];
__device__ int g_scan[NNODES];
__device__ int g_boff[NB1 + 32];
__device__ int g_rowptr[NNODES + 1];
__device__ int g_wcur[NNODES];

// ---------------- helpers ----------------------------------------------------
__device__ __forceinline__ float lrelu(float v) { return v >= 0.f ? v : 0.2f * v; }
__device__ __forceinline__ float4 lrelu4(float4 v) {
    return make_float4(lrelu(v.x), lrelu(v.y), lrelu(v.z), lrelu(v.w));
}
__device__ __forceinline__ float4 max4(float4 a, float4 b) {
    return make_float4(fmaxf(a.x, b.x), fmaxf(a.y, b.y),
                       fmaxf(a.z, b.z), fmaxf(a.w, b.w));
}
__device__ __forceinline__ float4 exp4(float4 a, float4 m) {
    return make_float4(__expf(a.x - m.x), __expf(a.y - m.y),
                       __expf(a.z - m.z), __expf(a.w - m.w));
}
__device__ __forceinline__ float4 wred_max4(float4 v) {
#pragma unroll
    for (int o = 16; o > 0; o >>= 1) {
        v.x = fmaxf(v.x, __shfl_xor_sync(0xffffffffu, v.x, o));
        v.y = fmaxf(v.y, __shfl_xor_sync(0xffffffffu, v.y, o));
        v.z = fmaxf(v.z, __shfl_xor_sync(0xffffffffu, v.z, o));
        v.w = fmaxf(v.w, __shfl_xor_sync(0xffffffffu, v.w, o));
    }
    return v;
}
__device__ __forceinline__ float4 wred_sum4(float4 v) {
#pragma unroll
    for (int o = 16; o > 0; o >>= 1) {
        v.x += __shfl_xor_sync(0xffffffffu, v.x, o);
        v.y += __shfl_xor_sync(0xffffffffu, v.y, o);
        v.z += __shfl_xor_sync(0xffffffffu, v.z, o);
        v.w += __shfl_xor_sync(0xffffffffu, v.w, o);
    }
    return v;
}
__device__ __forceinline__ unsigned f2tf32(float f) {
    unsigned u;
    asm("cvt.rna.tf32.f32 %0, %1;" : "=r"(u) : "f"(f));
    return u;
}
__device__ __forceinline__ void mma_tf32(float4& d, const unsigned a[4],
                                         unsigned b0, unsigned b1) {
    asm volatile(
        "mma.sync.aligned.m16n8k8.row.col.f32.tf32.tf32.f32 "
        "{%0,%1,%2,%3}, {%4,%5,%6,%7}, {%8,%9}, {%0,%1,%2,%3};\n"
        : "+f"(d.x), "+f"(d.y), "+f"(d.z), "+f"(d.w)
        : "r"(a[0]), "r"(a[1]), "r"(a[2]), "r"(a[3]), "r"(b0), "r"(b1));
}

// ---------------- fused: gemm1 (tf32 HMMA) || edge prep ----------------------
#define GB1 ((NNODES + 127) / 128)          // 782 gemm blocks
#define PB  ((ETOT + 255) / 256)            // 6641 prep blocks

__global__ void __launch_bounds__(256) k_gemm1_prep(const float* __restrict__ A,
                                                    const float* __restrict__ B,
                                                    const void* __restrict__ ei_raw) {
    __shared__ unsigned As[128][36];
    __shared__ unsigned Bs[32][136];

    if (blockIdx.x >= GB1) {
        // ---- edge prep: dtype-robust decode + degree histogram ----
        int e = (blockIdx.x - GB1) * 256 + threadIdx.x;
        if (e >= ETOT) return;
        int s, d;
        if (e >= E_IN) {
            s = d = e - E_IN;
        } else {
            const long long* e64 = (const long long*)ei_raw;
            bool is64 = true;
#pragma unroll
            for (int q = 0; q < 4; q++) {
                long long v = e64[q];
                if (v < 0 || v >= NNODES) is64 = false;
            }
            if (is64) {
                s = (int)e64[e];
                d = (int)e64[(size_t)E_IN + e];
            } else {
                const int* e32 = (const int*)ei_raw;
                s = e32[e];
                d = e32[E_IN + e];
            }
        }
        g_esrc[e] = s;
        g_edst[e] = d;
        atomicAdd(&g_deg[d], 1);
        return;
    }

    // ---- gemm1: 128x128 tile, BK=32, 8 warps, warp tile 32x64 ----
    const int tid  = threadIdx.x;
    const int lane = tid & 31, wid = tid >> 5;
    const int wm = (wid & 3) * 32;
    const int wn = (wid >> 2) * 64;
    const int row0 = blockIdx.x * 128;
    const int g = lane >> 2, tg = lane & 3;

    float4 acc[2][8];
#pragma unroll
    for (int mt = 0; mt < 2; mt++)
#pragma unroll
        for (int nt = 0; nt < 8; nt++) acc[mt][nt] = make_float4(0, 0, 0, 0);

    for (int k0 = 0; k0 < FIN; k0 += 32) {
#pragma unroll
        for (int q = 0; q < 4; q++) {
            int f4 = tid + q * 256;
            int r = f4 >> 3, c = (f4 & 7) * 4;
            float4 v = make_float4(0, 0, 0, 0);
            int gr = row0 + r;
            if (gr < NNODES) v = *(const float4*)&A[(size_t)gr * FIN + k0 + c];
            *(uint4*)&As[r][c] =
                make_uint4(f2tf32(v.x), f2tf32(v.y), f2tf32(v.z), f2tf32(v.w));
        }
#pragma unroll
        for (int q = 0; q < 4; q++) {
            int f4 = tid + q * 256;
            int r = f4 >> 5, c = (f4 & 31) * 4;
            float4 v = *(const float4*)&B[(size_t)(k0 + r) * F1 + c];
            *(uint4*)&Bs[r][c] =
                make_uint4(f2tf32(v.x), f2tf32(v.y), f2tf32(v.z), f2tf32(v.w));
        }
        __syncthreads();

#pragma unroll
        for (int kk = 0; kk < 32; kk += 8) {
            unsigned a[2][4];
#pragma unroll
            for (int mt = 0; mt < 2; mt++) {
                int rb = wm + mt * 16;
                a[mt][0] = As[rb + g][kk + tg];
                a[mt][1] = As[rb + 8 + g][kk + tg];
                a[mt][2] = As[rb + g][kk + tg + 4];
                a[mt][3] = As[rb + 8 + g][kk + tg + 4];
            }
#pragma unroll
            for (int nt = 0; nt < 8; nt++) {
                unsigned b0 = Bs[kk + tg][wn + nt * 8 + g];
                unsigned b1 = Bs[kk + 4 + tg][wn + nt * 8 + g];
                mma_tf32(acc[0][nt], a[0], b0, b1);
                mma_tf32(acc[1][nt], a[1], b0, b1);
            }
        }
        __syncthreads();
    }

#pragma unroll
    for (int mt = 0; mt < 2; mt++) {
#pragma unroll
        for (int nt = 0; nt < 8; nt++) {
            int r = row0 + wm + mt * 16 + g;
            int c = wn + nt * 8 + tg * 2;
            if (r < NNODES) {
                *(float2*)&g_h1[(size_t)r * F1 + c] =
                    make_float2(acc[mt][nt].x, acc[mt][nt].y);
                *(__half2*)&g_h1h[(size_t)r * F1 + c] =
                    __floats2half2_rn(acc[mt][nt].x, acc[mt][nt].y);
            }
            if (r + 8 < NNODES) {
                *(float2*)&g_h1[(size_t)(r + 8) * F1 + c] =
                    make_float2(acc[mt][nt].z, acc[mt][nt].w);
                *(__half2*)&g_h1h[(size_t)(r + 8) * F1 + c] =
                    __floats2half2_rn(acc[mt][nt].z, acc[mt][nt].w);
            }
        }
    }
}

// ---------------- fused: att1 || scan1 (512-thread blocks) --------------------
#define AB1 ((NNODES * NH1 + 511) / 512)    // 782 att1 blocks

__global__ void __launch_bounds__(512) k_att1_scan1(const float* __restrict__ att_s,
                                                    const float* __restrict__ att_d) {
    if (blockIdx.x < AB1) {
        __shared__ float ss[F1], sd[F1];
        if (threadIdx.x < F1) { ss[threadIdx.x] = att_s[threadIdx.x];
                                sd[threadIdx.x] = att_d[threadIdx.x]; }
        __syncthreads();
        int i = blockIdx.x * 512 + threadIdx.x;
        if (i >= NNODES * NH1) return;
        int n = i >> 2, h = i & 3;
        const float4* hv = (const float4*)&g_h1[(size_t)n * F1 + h * 32];
        const float4* sv = (const float4*)&ss[h * 32];
        const float4* dv = (const float4*)&sd[h * 32];
        float s = 0.f, d = 0.f;
#pragma unroll
        for (int q = 0; q < 8; q++) {
            float4 hh = hv[q], a = sv[q], b = dv[q];
            s += hh.x * a.x + hh.y * a.y + hh.z * a.z + hh.w * a.w;
            d += hh.x * b.x + hh.y * b.y + hh.z * b.z + hh.w * b.w;
        }
        g_asrc1[i] = s;
        g_adst1[i] = d;
        return;
    }

    // ---- scan1: per-block inclusive scan of degrees ----
    int t = threadIdx.x, b = blockIdx.x - AB1;
    int i = b * SCAN_B + t;
    int val = (i < NNODES) ? g_deg[i] : 0;
    int lane = t & 31, wid = t >> 5;
    int v = val;
#pragma unroll
    for (int o = 1; o < 32; o <<= 1) {
        int u = __shfl_up_sync(0xffffffffu, v, o);
        if (lane >= o) v += u;
    }
    __shared__ int wsum[SCAN_B / 32];
    if (lane == 31) wsum[wid] = v;
    __syncthreads();
    if (wid == 0) {
        int w = (lane < SCAN_B / 32) ? wsum[lane] : 0;
#pragma unroll
        for (int o = 1; o < 32; o <<= 1) {
            int u = __shfl_up_sync(0xffffffffu, w, o);
            if (lane >= o) w += u;
        }
        if (lane < SCAN_B / 32) wsum[lane] = w;
    }
    __syncthreads();
    int incl = v + (wid ? wsum[wid - 1] : 0);
    if (i < NNODES) g_scan[i] = incl;
    if (t == SCAN_B - 1) g_boff[b] = incl;
}

// ---------------- scan phases 2,3 + scatter ------------------------------------
__global__ void k_scan2() {
    int t = threadIdx.x;
    int val = (t < NB1) ? g_boff[t] : 0;
    int lane = t & 31, wid = t >> 5;
    int v = val;
#pragma unroll
    for (int o = 1; o < 32; o <<= 1) {
        int u = __shfl_up_sync(0xffffffffu, v, o);
        if (lane >= o) v += u;
    }
    __shared__ int wsum[8];
    if (lane == 31) wsum[wid] = v;
    __syncthreads();
    if (wid == 0) {
        int w = (lane < 8) ? wsum[lane] : 0;
#pragma unroll
        for (int o = 1; o < 8; o <<= 1) {
            int u = __shfl_up_sync(0xffffffffu, w, o);
            if (lane >= o) w += u;
        }
        if (lane < 8) wsum[lane] = w;
    }
    __syncthreads();
    int incl = v + (wid ? wsum[wid - 1] : 0);
    if (t < NB1) g_boff[t] = incl - val;
}
__global__ void k_scan3() {
    int i = blockIdx.x * blockDim.x + threadIdx.x;
    if (i >= NNODES) return;
    int base = g_boff[i / SCAN_B];
    int excl = base + g_scan[i] - g_deg[i];
    g_rowptr[i] = excl;
    g_wcur[i]   = excl;
    if (i == 0) g_rowptr[NNODES] = ETOT;
}
__global__ void k_scatter() {
    int e = blockIdx.x * blockDim.x + threadIdx.x;
    if (e >= ETOT) return;
    int d = g_edst[e];
    int pos = atomicAdd(&g_wcur[d], 1);
    g_csrc[pos] = g_esrc[e];
}

// ---------------- gemm2: g_h2 = g_agg1 @ W2, tf32 HMMA + fp16 shadow ----------
__global__ void __launch_bounds__(256) gemm2_kernel(const float* __restrict__ B) {
    __shared__ unsigned As[128][36];
    __shared__ unsigned Bs[32][72];
    const float* A = g_agg1;
    const int tid  = threadIdx.x;
    const int lane = tid & 31, wid = tid >> 5;
    const int wm = (wid & 3) * 32;
    const int wn = (wid >> 2) * 32;
    const int row0 = blockIdx.x * 128;
    const int g = lane >> 2, tg = lane & 3;

    float4 acc[2][4];
#pragma unroll
    for (int mt = 0; mt < 2; mt++)
#pragma unroll
        for (int nt = 0; nt < 4; nt++) acc[mt][nt] = make_float4(0, 0, 0, 0);

    for (int k0 = 0; k0 < F1; k0 += 32) {
#pragma unroll
        for (int q = 0; q < 4; q++) {
            int f4 = tid + q * 256;
            int r = f4 >> 3, c = (f4 & 7) * 4;
            float4 v = make_float4(0, 0, 0, 0);
            int gr = row0 + r;
            if (gr < NNODES) v = *(const float4*)&A[(size_t)gr * F1 + k0 + c];
            *(uint4*)&As[r][c] =
                make_uint4(f2tf32(v.x), f2tf32(v.y), f2tf32(v.z), f2tf32(v.w));
        }
#pragma unroll
        for (int q = 0; q < 2; q++) {
            int f4 = tid + q * 256;
            int r = f4 >> 4, c = (f4 & 15) * 4;
            float4 v = *(const float4*)&B[(size_t)(k0 + r) * CO + c];
            *(uint4*)&Bs[r][c] =
                make_uint4(f2tf32(v.x), f2tf32(v.y), f2tf32(v.z), f2tf32(v.w));
        }
        __syncthreads();

#pragma unroll
        for (int kk = 0; kk < 32; kk += 8) {
            unsigned a[2][4];
#pragma unroll
            for (int mt = 0; mt < 2; mt++) {
                int rb = wm + mt * 16;
                a[mt][0] = As[rb + g][kk + tg];
                a[mt][1] = As[rb + 8 + g][kk + tg];
                a[mt][2] = As[rb + g][kk + tg + 4];
                a[mt][3] = As[rb + 8 + g][kk + tg + 4];
            }
#pragma unroll
            for (int nt = 0; nt < 4; nt++) {
                unsigned b0 = Bs[kk + tg][wn + nt * 8 + g];
                unsigned b1 = Bs[kk + 4 + tg][wn + nt * 8 + g];
                mma_tf32(acc[0][nt], a[0], b0, b1);
                mma_tf32(acc[1][nt], a[1], b0, b1);
            }
        }
        __syncthreads();
    }

#pragma unroll
    for (int mt = 0; mt < 2; mt++) {
#pragma unroll
        for (int nt = 0; nt < 4; nt++) {
            int r = row0 + wm + mt * 16 + g;
            int c = wn + nt * 8 + tg * 2;
            if (r < NNODES) {
                *(float2*)&g_h2[(size_t)r * CO + c] =
                    make_float2(acc[mt][nt].x, acc[mt][nt].y);
                *(__half2*)&g_h2h[(size_t)r * CO + c] =
                    __floats2half2_rn(acc[mt][nt].x, acc[mt][nt].y);
            }
            if (r + 8 < NNODES) {
                *(float2*)&g_h2[(size_t)(r + 8) * CO + c] =
                    make_float2(acc[mt][nt].z, acc[mt][nt].w);
                *(__half2*)&g_h2h[(size_t)(r + 8) * CO + c] =
                    __floats2half2_rn(acc[mt][nt].z, acc[mt][nt].w);
            }
        }
    }
}

// ---------------- att2 ---------------------------------------------------------
__global__ void k_att2(const float* __restrict__ att_s,
                       const float* __restrict__ att_d) {
    __shared__ float ss[CO], sd[CO];
    if (threadIdx.x < CO) { ss[threadIdx.x] = att_s[threadIdx.x];
                            sd[threadIdx.x] = att_d[threadIdx.x]; }
    __syncthreads();
    int n = blockIdx.x * blockDim.x + threadIdx.x;
    if (n >= NNODES) return;
    const float4* hv = (const float4*)&g_h2[(size_t)n * CO];
    const float4* sv = (const float4*)ss;
    const float4* dv = (const float4*)sd;
    float s = 0.f, d = 0.f;
#pragma unroll
    for (int q = 0; q < CO / 4; q++) {
        float4 hh = hv[q], a = sv[q], b = dv[q];
        s += hh.x * a.x + hh.y * a.y + hh.z * a.z + hh.w * a.w;
        d += hh.x * b.x + hh.y * b.y + hh.z * b.z + hh.w * b.w;
    }
    g_asrc2[n] = s;
    g_adst2[n] = d;
}

// ---------------- layer-1: fused softmax+aggregate (fp16 gathers) -------------
__global__ void __launch_bounds__(256) k_l1(const float* __restrict__ b1) {
    __shared__ float4 sal[8][64];
    int w = (blockIdx.x * blockDim.x + threadIdx.x) >> 5;
    if (w >= NNODES) return;
    const int n = w, lane = threadIdx.x & 31, ws = (threadIdx.x >> 5);
    const int beg = g_rowptr[n], end = g_rowptr[n + 1];
    const int deg = end - beg;
    const float4 ad = *(const float4*)&g_adst1[n * 4];
    const int h = lane >> 3;
    float4 acc = make_float4(0, 0, 0, 0);

    if (deg <= 64) {
        int s0 = 0, s1 = 0;
        float4 e0 = make_float4(0, 0, 0, 0), e1 = e0;
        const int p0 = beg + lane, p1 = p0 + 32;
        const bool v0 = p0 < end, v1 = p1 < end;
        float4 mx = make_float4(-CUDART_INF_F, -CUDART_INF_F,
                                -CUDART_INF_F, -CUDART_INF_F);
        if (v0) {
            s0 = g_csrc[p0];
            e0 = lrelu4(make_float4(g_asrc1[s0 * 4 + 0] + ad.x,
                                    g_asrc1[s0 * 4 + 1] + ad.y,
                                    g_asrc1[s0 * 4 + 2] + ad.z,
                                    g_asrc1[s0 * 4 + 3] + ad.w));
            mx = max4(mx, e0);
        }
        if (v1) {
            s1 = g_csrc[p1];
            e1 = lrelu4(make_float4(g_asrc1[s1 * 4 + 0] + ad.x,
                                    g_asrc1[s1 * 4 + 1] + ad.y,
                                    g_asrc1[s1 * 4 + 2] + ad.z,
                                    g_asrc1[s1 * 4 + 3] + ad.w));
            mx = max4(mx, e1);
        }
        mx = wred_max4(mx);
        float4 sm = make_float4(0, 0, 0, 0);
        float4 x0 = make_float4(0, 0, 0, 0), x1 = x0;
        if (v0) { x0 = exp4(e0, mx); sm.x += x0.x; sm.y += x0.y; sm.z += x0.z; sm.w += x0.w; }
        if (v1) { x1 = exp4(e1, mx); sm.x += x1.x; sm.y += x1.y; sm.z += x1.z; sm.w += x1.w; }
        sm = wred_sum4(sm);
        float4 inv = make_float4(1.f / (sm.x + EPSV), 1.f / (sm.y + EPSV),
                                 1.f / (sm.z + EPSV), 1.f / (sm.w + EPSV));
        if (v0) sal[ws][lane] = make_float4(x0.x * inv.x, x0.y * inv.y,
                                            x0.z * inv.z, x0.w * inv.w);
        if (v1) sal[ws][lane + 32] = make_float4(x1.x * inv.x, x1.y * inv.y,
                                                 x1.z * inv.z, x1.w * inv.w);
        __syncwarp();
        for (int j = 0; j < deg; j++) {
            int sv = (j < 32) ? s0 : s1;
            int s = __shfl_sync(0xffffffffu, sv, j & 31);
            float alpha = ((const float*)&sal[ws][j])[h];
            const __half2* hp = (const __half2*)&g_h1h[(size_t)s * F1 + lane * 4];
            float2 f0 = __half22float2(hp[0]);
            float2 f1 = __half22float2(hp[1]);
            acc.x = fmaf(f0.x, alpha, acc.x);
            acc.y = fmaf(f0.y, alpha, acc.y);
            acc.z = fmaf(f1.x, alpha, acc.z);
            acc.w = fmaf(f1.y, alpha, acc.w);
        }
    } else {
        float4 mx = make_float4(-CUDART_INF_F, -CUDART_INF_F,
                                -CUDART_INF_F, -CUDART_INF_F);
        for (int p = beg + lane; p < end; p += 32) {
            int s = g_csrc[p];
            float4 e = lrelu4(make_float4(g_asrc1[s * 4 + 0] + ad.x,
                                          g_asrc1[s * 4 + 1] + ad.y,
                                          g_asrc1[s * 4 + 2] + ad.z,
                                          g_asrc1[s * 4 + 3] + ad.w));
            *(float4*)&g_ex1[(size_t)p * 4] = e;
            mx = max4(mx, e);
        }
        mx = wred_max4(mx);
        float4 sm = make_float4(0, 0, 0, 0);
        for (int p = beg + lane; p < end; p += 32) {
            float4 e = *(const float4*)&g_ex1[(size_t)p * 4];
            float4 ex = exp4(e, mx);
            *(float4*)&g_ex1[(size_t)p * 4] = ex;
            sm.x += ex.x; sm.y += ex.y; sm.z += ex.z; sm.w += ex.w;
        }
        sm = wred_sum4(sm);
        float4 inv = make_float4(1.f / (sm.x + EPSV), 1.f / (sm.y + EPSV),
                                 1.f / (sm.z + EPSV), 1.f / (sm.w + EPSV));
        __syncwarp();
        const float invh = (h == 0) ? inv.x : (h == 1) ? inv.y
                         : (h == 2) ? inv.z : inv.w;
        for (int p = beg; p < end; ++p) {
            int s = g_csrc[p];
            float alpha = g_ex1[(size_t)p * 4 + h] * invh;
            const __half2* hp = (const __half2*)&g_h1h[(size_t)s * F1 + lane * 4];
            float2 f0 = __half22float2(hp[0]);
            float2 f1 = __half22float2(hp[1]);
            acc.x = fmaf(f0.x, alpha, acc.x);
            acc.y = fmaf(f0.y, alpha, acc.y);
            acc.z = fmaf(f1.x, alpha, acc.z);
            acc.w = fmaf(f1.y, alpha, acc.w);
        }
    }

    float4 b = *(const float4*)&b1[lane * 4];
    float4 v = make_float4(acc.x + b.x, acc.y + b.y, acc.z + b.z, acc.w + b.w);
    v.x = v.x > 0.f ? v.x : expm1f(v.x);
    v.y = v.y > 0.f ? v.y : expm1f(v.y);
    v.z = v.z > 0.f ? v.z : expm1f(v.z);
    v.w = v.w > 0.f ? v.w : expm1f(v.w);
    *(float4*)&g_agg1[(size_t)n * F1 + lane * 4] = v;
}

// ---------------- layer-2: fused softmax+aggregate (fp16) + deg re-zero -------
#define GW2 ((NNODES * 32 + 255) / 256)     // 12500 main blocks
#define ZB2 ((NNODES + 255) / 256)          // 391 zeroing blocks

__global__ void __launch_bounds__(256) k_l2(const float* __restrict__ b2,
                                            float* __restrict__ out) {
    if (blockIdx.x >= GW2) {
        int i = (blockIdx.x - GW2) * 256 + threadIdx.x;
        if (i < NNODES) g_deg[i] = 0;    // restore invariant for next replay
        return;
    }
    __shared__ float sal[8][64];
    int w = (blockIdx.x * blockDim.x + threadIdx.x) >> 5;
    if (w >= NNODES) return;
    const int n = w, lane = threadIdx.x & 31, ws = (threadIdx.x >> 5);
    const int beg = g_rowptr[n], end = g_rowptr[n + 1];
    const int deg = end - beg;
    const float adn = g_adst2[n];
    float2 acc = make_float2(0, 0);

    if (deg <= 64) {
        int s0 = 0, s1 = 0;
        float e0 = 0.f, e1 = 0.f;
        const int p0 = beg + lane, p1 = p0 + 32;
        const bool v0 = p0 < end, v1 = p1 < end;
        float mx = -CUDART_INF_F;
        if (v0) { s0 = g_csrc[p0]; e0 = lrelu(g_asrc2[s0] + adn); mx = fmaxf(mx, e0); }
        if (v1) { s1 = g_csrc[p1]; e1 = lrelu(g_asrc2[s1] + adn); mx = fmaxf(mx, e1); }
#pragma unroll
        for (int o = 16; o > 0; o >>= 1)
            mx = fmaxf(mx, __shfl_xor_sync(0xffffffffu, mx, o));
        float sm = 0.f, x0 = 0.f, x1 = 0.f;
        if (v0) { x0 = __expf(e0 - mx); sm += x0; }
        if (v1) { x1 = __expf(e1 - mx); sm += x1; }
#pragma unroll
        for (int o = 16; o > 0; o >>= 1) sm += __shfl_xor_sync(0xffffffffu, sm, o);
        float inv = 1.f / (sm + EPSV);
        if (v0) sal[ws][lane]      = x0 * inv;
        if (v1) sal[ws][lane + 32] = x1 * inv;
        __syncwarp();
        for (int j = 0; j < deg; j++) {
            int sv = (j < 32) ? s0 : s1;
            int s = __shfl_sync(0xffffffffu, sv, j & 31);
            float alpha = sal[ws][j];
            float2 hv = __half22float2(
                *(const __half2*)&g_h2h[(size_t)s * CO + lane * 2]);
            acc.x = fmaf(hv.x, alpha, acc.x);
            acc.y = fmaf(hv.y, alpha, acc.y);
        }
    } else {
        float mx = -CUDART_INF_F;
        for (int p = beg + lane; p < end; p += 32) {
            int s = g_csrc[p];
            float e = lrelu(g_asrc2[s] + adn);
            g_ex2[p] = e;
            mx = fmaxf(mx, e);
        }
#pragma unroll
        for (int o = 16; o > 0; o >>= 1)
            mx = fmaxf(mx, __shfl_xor_sync(0xffffffffu, mx, o));
        float sm = 0.f;
        for (int p = beg + lane; p < end; p += 32) {
            float ex = __expf(g_ex2[p] - mx);
            g_ex2[p] = ex;
            sm += ex;
        }
#pragma unroll
        for (int o = 16; o > 0; o >>= 1) sm += __shfl_xor_sync(0xffffffffu, sm, o);
        float inv = 1.f / (sm + EPSV);
        __syncwarp();
        for (int p = beg; p < end; ++p) {
            int s = g_csrc[p];
            float alpha = g_ex2[p] * inv;
            float2 hv = __half22float2(
                *(const __half2*)&g_h2h[(size_t)s * CO + lane * 2]);
            acc.x = fmaf(hv.x, alpha, acc.x);
            acc.y = fmaf(hv.y, alpha, acc.y);
        }
    }

    float2 b = *(const float2*)&b2[lane * 2];
    *(float2*)&out[(size_t)n * CO + lane * 2] = make_float2(acc.x + b.x, acc.y + b.y);
}

// ---------------- launcher -------------------------------------------------------
extern "C" void kernel_launch(void* const* d_in, const int* in_sizes, int n_in,
                              void* d_out, int out_size) {
    const float* x   = (const float*)d_in[0];
    const void*  ei  = d_in[1];
    const float* W1  = (const float*)d_in[2];
    const float* as1 = (const float*)d_in[3];
    const float* ad1 = (const float*)d_in[4];
    const float* b1  = (const float*)d_in[5];
    const float* W2  = (const float*)d_in[6];
    const float* as2 = (const float*)d_in[7];
    const float* ad2 = (const float*)d_in[8];
    const float* b2  = (const float*)d_in[9];
    float* out = (float*)d_out;

    (void)in_sizes; (void)n_in; (void)out_size;

    const int gNode = (NNODES + TPB - 1) / TPB;
    const int gEdge = (ETOT + TPB - 1) / TPB;

    // gemm1 || edge prep (deg is zero: static init on first run, k_l2 tail after)
    k_gemm1_prep<<<GB1 + PB, 256>>>(x, W1, ei);
    // att1 || scan1
    k_att1_scan1<<<AB1 + NB1, SCAN_B>>>(as1, ad1);
    k_scan2<<<1, 256>>>();
    k_scan3<<<gNode, TPB>>>();
    k_scatter<<<gEdge, TPB>>>();

    k_l1<<<GW2, TPB>>>(b1);

    gemm2_kernel<<<(NNODES + 127) / 128, 256>>>(W2);
    k_att2<<<gNode, TPB>>>(as2, ad2);
    k_l2<<<GW2 + ZB2, TPB>>>(b2, out);
}

// round 14
// speedup vs baseline: 1.0196x; 1.0137x over previous
#include <cuda_runtime.h>
#include <cuda_fp16.h>
#include <math_constants.h>

// ---------------------------------------------------------------------------
// GAT 2-layer forward, fixed shapes. CSR-based, zero float atomics.
// R14: fp16 gathers as single LDG.64/LDG.32 (halves l1tex wavefronts in agg
//      loops), x2 unrolled aggregate loops, scan2+scan3 fused. Launch order
//      puts k_scatter at the profiler's capture index.
// ---------------------------------------------------------------------------

#define NNODES 100000
#define E_IN   1600000
#define ETOT   (E_IN + NNODES)
#define NH1    4
#define F1     128
#define FIN    256
#define CO     64
#define EPSV   1e-16f
#define SCAN_B 512
#define NB1    ((NNODES + SCAN_B - 1) / SCAN_B)   // 196

static const int TPB = 256;

// ---------------- device scratch (static, 16B-aligned) ----------------------
__device__ __align__(16) float  g_h1  [(size_t)NNODES * F1];
__device__ __align__(16) __half g_h1h [(size_t)NNODES * F1];
__device__ __align__(16) float  g_agg1[(size_t)NNODES * F1];
__device__ __align__(16) float  g_h2  [(size_t)NNODES * CO];
__device__ __align__(16) __half g_h2h [(size_t)NNODES * CO];
__device__ __align__(16) float  g_asrc1[NNODES * NH1];
__device__ __align__(16) float  g_adst1[NNODES * NH1];
__device__ __align__(16) float  g_ex1 [(size_t)ETOT * NH1];   // deg>64 fallback
__device__ __align__(16) float  g_asrc2[NNODES];
__device__ __align__(16) float  g_adst2[NNODES];
__device__ __align__(16) float  g_ex2 [ETOT];                 // deg>64 fallback
// CSR machinery (g_deg zero-initialized statically; re-zeroed by k_l2 tail)
__device__ int g_esrc[ETOT];
__device__ int g_edst[ETOT];
__device__ int g_csrc[ETOT];
__device__ int g_deg [NNODES];
__device__ int g_scan[NNODES];
__device__ int g_boff[NB1 + 32];
__device__ int g_rowptr[NNODES + 1];
__device__ int g_wcur[NNODES];

// ---------------- helpers ----------------------------------------------------
__device__ __forceinline__ float lrelu(float v) { return v >= 0.f ? v : 0.2f * v; }
__device__ __forceinline__ float4 lrelu4(float4 v) {
    return make_float4(lrelu(v.x), lrelu(v.y), lrelu(v.z), lrelu(v.w));
}
__device__ __forceinline__ float4 max4(float4 a, float4 b) {
    return make_float4(fmaxf(a.x, b.x), fmaxf(a.y, b.y),
                       fmaxf(a.z, b.z), fmaxf(a.w, b.w));
}
__device__ __forceinline__ float4 exp4(float4 a, float4 m) {
    return make_float4(__expf(a.x - m.x), __expf(a.y - m.y),
                       __expf(a.z - m.z), __expf(a.w - m.w));
}
__device__ __forceinline__ float4 wred_max4(float4 v) {
#pragma unroll
    for (int o = 16; o > 0; o >>= 1) {
        v.x = fmaxf(v.x, __shfl_xor_sync(0xffffffffu, v.x, o));
        v.y = fmaxf(v.y, __shfl_xor_sync(0xffffffffu, v.y, o));
        v.z = fmaxf(v.z, __shfl_xor_sync(0xffffffffu, v.z, o));
        v.w = fmaxf(v.w, __shfl_xor_sync(0xffffffffu, v.w, o));
    }
    return v;
}
__device__ __forceinline__ float4 wred_sum4(float4 v) {
#pragma unroll
    for (int o = 16; o > 0; o >>= 1) {
        v.x += __shfl_xor_sync(0xffffffffu, v.x, o);
        v.y += __shfl_xor_sync(0xffffffffu, v.y, o);
        v.z += __shfl_xor_sync(0xffffffffu, v.z, o);
        v.w += __shfl_xor_sync(0xffffffffu, v.w, o);
    }
    return v;
}
__device__ __forceinline__ unsigned f2tf32(float f) {
    unsigned u;
    asm("cvt.rna.tf32.f32 %0, %1;" : "=r"(u) : "f"(f));
    return u;
}
__device__ __forceinline__ void mma_tf32(float4& d, const unsigned a[4],
                                         unsigned b0, unsigned b1) {
    asm volatile(
        "mma.sync.aligned.m16n8k8.row.col.f32.tf32.tf32.f32 "
        "{%0,%1,%2,%3}, {%4,%5,%6,%7}, {%8,%9}, {%0,%1,%2,%3};\n"
        : "+f"(d.x), "+f"(d.y), "+f"(d.z), "+f"(d.w)
        : "r"(a[0]), "r"(a[1]), "r"(a[2]), "r"(a[3]), "r"(b0), "r"(b1));
}
// single 8-byte fp16 gather (LDG.64) -> 4 floats
__device__ __forceinline__ float4 ld_h4(const __half* p) {
    float2 raw = *(const float2*)p;
    __half2 p0 = *(__half2*)&raw.x;
    __half2 p1 = *(__half2*)&raw.y;
    float2 f0 = __half22float2(p0), f1 = __half22float2(p1);
    return make_float4(f0.x, f0.y, f1.x, f1.y);
}
// single 4-byte fp16 gather (LDG.32) -> 2 floats
__device__ __forceinline__ float2 ld_h2(const __half* p) {
    float raw = *(const float*)p;
    return __half22float2(*(__half2*)&raw);
}

// ---------------- fused: gemm1 (tf32 HMMA) || edge prep ----------------------
#define GB1 ((NNODES + 127) / 128)          // 782 gemm blocks
#define PB  ((ETOT + 255) / 256)            // 6641 prep blocks

__global__ void __launch_bounds__(256) k_gemm1_prep(const float* __restrict__ A,
                                                    const float* __restrict__ B,
                                                    const void* __restrict__ ei_raw) {
    __shared__ unsigned As[128][36];
    __shared__ unsigned Bs[32][136];

    if (blockIdx.x >= GB1) {
        int e = (blockIdx.x - GB1) * 256 + threadIdx.x;
        if (e >= ETOT) return;
        int s, d;
        if (e >= E_IN) {
            s = d = e - E_IN;
        } else {
            const long long* e64 = (const long long*)ei_raw;
            bool is64 = true;
#pragma unroll
            for (int q = 0; q < 4; q++) {
                long long v = e64[q];
                if (v < 0 || v >= NNODES) is64 = false;
            }
            if (is64) {
                s = (int)e64[e];
                d = (int)e64[(size_t)E_IN + e];
            } else {
                const int* e32 = (const int*)ei_raw;
                s = e32[e];
                d = e32[E_IN + e];
            }
        }
        g_esrc[e] = s;
        g_edst[e] = d;
        atomicAdd(&g_deg[d], 1);
        return;
    }

    const int tid  = threadIdx.x;
    const int lane = tid & 31, wid = tid >> 5;
    const int wm = (wid & 3) * 32;
    const int wn = (wid >> 2) * 64;
    const int row0 = blockIdx.x * 128;
    const int g = lane >> 2, tg = lane & 3;

    float4 acc[2][8];
#pragma unroll
    for (int mt = 0; mt < 2; mt++)
#pragma unroll
        for (int nt = 0; nt < 8; nt++) acc[mt][nt] = make_float4(0, 0, 0, 0);

    for (int k0 = 0; k0 < FIN; k0 += 32) {
#pragma unroll
        for (int q = 0; q < 4; q++) {
            int f4 = tid + q * 256;
            int r = f4 >> 3, c = (f4 & 7) * 4;
            float4 v = make_float4(0, 0, 0, 0);
            int gr = row0 + r;
            if (gr < NNODES) v = *(const float4*)&A[(size_t)gr * FIN + k0 + c];
            *(uint4*)&As[r][c] =
                make_uint4(f2tf32(v.x), f2tf32(v.y), f2tf32(v.z), f2tf32(v.w));
        }
#pragma unroll
        for (int q = 0; q < 4; q++) {
            int f4 = tid + q * 256;
            int r = f4 >> 5, c = (f4 & 31) * 4;
            float4 v = *(const float4*)&B[(size_t)(k0 + r) * F1 + c];
            *(uint4*)&Bs[r][c] =
                make_uint4(f2tf32(v.x), f2tf32(v.y), f2tf32(v.z), f2tf32(v.w));
        }
        __syncthreads();

#pragma unroll
        for (int kk = 0; kk < 32; kk += 8) {
            unsigned a[2][4];
#pragma unroll
            for (int mt = 0; mt < 2; mt++) {
                int rb = wm + mt * 16;
                a[mt][0] = As[rb + g][kk + tg];
                a[mt][1] = As[rb + 8 + g][kk + tg];
                a[mt][2] = As[rb + g][kk + tg + 4];
                a[mt][3] = As[rb + 8 + g][kk + tg + 4];
            }
#pragma unroll
            for (int nt = 0; nt < 8; nt++) {
                unsigned b0 = Bs[kk + tg][wn + nt * 8 + g];
                unsigned b1 = Bs[kk + 4 + tg][wn + nt * 8 + g];
                mma_tf32(acc[0][nt], a[0], b0, b1);
                mma_tf32(acc[1][nt], a[1], b0, b1);
            }
        }
        __syncthreads();
    }

#pragma unroll
    for (int mt = 0; mt < 2; mt++) {
#pragma unroll
        for (int nt = 0; nt < 8; nt++) {
            int r = row0 + wm + mt * 16 + g;
            int c = wn + nt * 8 + tg * 2;
            if (r < NNODES) {
                *(float2*)&g_h1[(size_t)r * F1 + c] =
                    make_float2(acc[mt][nt].x, acc[mt][nt].y);
                *(__half2*)&g_h1h[(size_t)r * F1 + c] =
                    __floats2half2_rn(acc[mt][nt].x, acc[mt][nt].y);
            }
            if (r + 8 < NNODES) {
                *(float2*)&g_h1[(size_t)(r + 8) * F1 + c] =
                    make_float2(acc[mt][nt].z, acc[mt][nt].w);
                *(__half2*)&g_h1h[(size_t)(r + 8) * F1 + c] =
                    __floats2half2_rn(acc[mt][nt].z, acc[mt][nt].w);
            }
        }
    }
}

// ---------------- fused: att1 || scan1 (512-thread blocks) --------------------
#define AB1 ((NNODES * NH1 + 511) / 512)    // 782 att1 blocks

__global__ void __launch_bounds__(512) k_att1_scan1(const float* __restrict__ att_s,
                                                    const float* __restrict__ att_d) {
    if (blockIdx.x < AB1) {
        __shared__ float ss[F1], sd[F1];
        if (threadIdx.x < F1) { ss[threadIdx.x] = att_s[threadIdx.x];
                                sd[threadIdx.x] = att_d[threadIdx.x]; }
        __syncthreads();
        int i = blockIdx.x * 512 + threadIdx.x;
        if (i >= NNODES * NH1) return;
        int n = i >> 2, h = i & 3;
        const float4* hv = (const float4*)&g_h1[(size_t)n * F1 + h * 32];
        const float4* sv = (const float4*)&ss[h * 32];
        const float4* dv = (const float4*)&sd[h * 32];
        float s = 0.f, d = 0.f;
#pragma unroll
        for (int q = 0; q < 8; q++) {
            float4 hh = hv[q], a = sv[q], b = dv[q];
            s += hh.x * a.x + hh.y * a.y + hh.z * a.z + hh.w * a.w;
            d += hh.x * b.x + hh.y * b.y + hh.z * b.z + hh.w * b.w;
        }
        g_asrc1[i] = s;
        g_adst1[i] = d;
        return;
    }

    int t = threadIdx.x, b = blockIdx.x - AB1;
    int i = b * SCAN_B + t;
    int val = (i < NNODES) ? g_deg[i] : 0;
    int lane = t & 31, wid = t >> 5;
    int v = val;
#pragma unroll
    for (int o = 1; o < 32; o <<= 1) {
        int u = __shfl_up_sync(0xffffffffu, v, o);
        if (lane >= o) v += u;
    }
    __shared__ int wsum[SCAN_B / 32];
    if (lane == 31) wsum[wid] = v;
    __syncthreads();
    if (wid == 0) {
        int w = (lane < SCAN_B / 32) ? wsum[lane] : 0;
#pragma unroll
        for (int o = 1; o < 32; o <<= 1) {
            int u = __shfl_up_sync(0xffffffffu, w, o);
            if (lane >= o) w += u;
        }
        if (lane < SCAN_B / 32) wsum[lane] = w;
    }
    __syncthreads();
    int incl = v + (wid ? wsum[wid - 1] : 0);
    if (i < NNODES) g_scan[i] = incl;
    if (t == SCAN_B - 1) g_boff[b] = incl;
}

// ---------------- fused scan phases 2+3 ---------------------------------------
// Each block computes its own prefix over the 196 block totals (7 warp loads),
// then emits exclusive rowptr/wcur. Removes the single-block scan2 launch.
__global__ void __launch_bounds__(SCAN_B) k_scan23() {
    __shared__ int s_pref;
    const int b = blockIdx.x;
    if (threadIdx.x < 32) {
        int lane = threadIdx.x;
        int sum = 0;
        for (int q = lane; q < b; q += 32) sum += g_boff[q];
#pragma unroll
        for (int o = 16; o > 0; o >>= 1)
            sum += __shfl_xor_sync(0xffffffffu, sum, o);
        if (lane == 0) s_pref = sum;
    }
    __syncthreads();
    int i = b * SCAN_B + threadIdx.x;
    if (i >= NNODES) return;
    int excl = s_pref + g_scan[i] - g_deg[i];
    g_rowptr[i] = excl;
    g_wcur[i]   = excl;
    if (i == 0) g_rowptr[NNODES] = ETOT;
}

__global__ void k_scatter() {
    int e = blockIdx.x * blockDim.x + threadIdx.x;
    if (e >= ETOT) return;
    int d = g_edst[e];
    int pos = atomicAdd(&g_wcur[d], 1);
    g_csrc[pos] = g_esrc[e];
}

// ---------------- gemm2: g_h2 = g_agg1 @ W2, tf32 HMMA + fp16 shadow ----------
__global__ void __launch_bounds__(256) gemm2_kernel(const float* __restrict__ B) {
    __shared__ unsigned As[128][36];
    __shared__ unsigned Bs[32][72];
    const float* A = g_agg1;
    const int tid  = threadIdx.x;
    const int lane = tid & 31, wid = tid >> 5;
    const int wm = (wid & 3) * 32;
    const int wn = (wid >> 2) * 32;
    const int row0 = blockIdx.x * 128;
    const int g = lane >> 2, tg = lane & 3;

    float4 acc[2][4];
#pragma unroll
    for (int mt = 0; mt < 2; mt++)
#pragma unroll
        for (int nt = 0; nt < 4; nt++) acc[mt][nt] = make_float4(0, 0, 0, 0);

    for (int k0 = 0; k0 < F1; k0 += 32) {
#pragma unroll
        for (int q = 0; q < 4; q++) {
            int f4 = tid + q * 256;
            int r = f4 >> 3, c = (f4 & 7) * 4;
            float4 v = make_float4(0, 0, 0, 0);
            int gr = row0 + r;
            if (gr < NNODES) v = *(const float4*)&A[(size_t)gr * F1 + k0 + c];
            *(uint4*)&As[r][c] =
                make_uint4(f2tf32(v.x), f2tf32(v.y), f2tf32(v.z), f2tf32(v.w));
        }
#pragma unroll
        for (int q = 0; q < 2; q++) {
            int f4 = tid + q * 256;
            int r = f4 >> 4, c = (f4 & 15) * 4;
            float4 v = *(const float4*)&B[(size_t)(k0 + r) * CO + c];
            *(uint4*)&Bs[r][c] =
                make_uint4(f2tf32(v.x), f2tf32(v.y), f2tf32(v.z), f2tf32(v.w));
        }
        __syncthreads();

#pragma unroll
        for (int kk = 0; kk < 32; kk += 8) {
            unsigned a[2][4];
#pragma unroll
            for (int mt = 0; mt < 2; mt++) {
                int rb = wm + mt * 16;
                a[mt][0] = As[rb + g][kk + tg];
                a[mt][1] = As[rb + 8 + g][kk + tg];
                a[mt][2] = As[rb + g][kk + tg + 4];
                a[mt][3] = As[rb + 8 + g][kk + tg + 4];
            }
#pragma unroll
            for (int nt = 0; nt < 4; nt++) {
                unsigned b0 = Bs[kk + tg][wn + nt * 8 + g];
                unsigned b1 = Bs[kk + 4 + tg][wn + nt * 8 + g];
                mma_tf32(acc[0][nt], a[0], b0, b1);
                mma_tf32(acc[1][nt], a[1], b0, b1);
            }
        }
        __syncthreads();
    }

#pragma unroll
    for (int mt = 0; mt < 2; mt++) {
#pragma unroll
        for (int nt = 0; nt < 4; nt++) {
            int r = row0 + wm + mt * 16 + g;
            int c = wn + nt * 8 + tg * 2;
            if (r < NNODES) {
                *(float2*)&g_h2[(size_t)r * CO + c] =
                    make_float2(acc[mt][nt].x, acc[mt][nt].y);
                *(__half2*)&g_h2h[(size_t)r * CO + c] =
                    __floats2half2_rn(acc[mt][nt].x, acc[mt][nt].y);
            }
            if (r + 8 < NNODES) {
                *(float2*)&g_h2[(size_t)(r + 8) * CO + c] =
                    make_float2(acc[mt][nt].z, acc[mt][nt].w);
                *(__half2*)&g_h2h[(size_t)(r + 8) * CO + c] =
                    __floats2half2_rn(acc[mt][nt].z, acc[mt][nt].w);
            }
        }
    }
}

// ---------------- att2 ---------------------------------------------------------
__global__ void k_att2(const float* __restrict__ att_s,
                       const float* __restrict__ att_d) {
    __shared__ float ss[CO], sd[CO];
    if (threadIdx.x < CO) { ss[threadIdx.x] = att_s[threadIdx.x];
                            sd[threadIdx.x] = att_d[threadIdx.x]; }
    __syncthreads();
    int n = blockIdx.x * blockDim.x + threadIdx.x;
    if (n >= NNODES) return;
    const float4* hv = (const float4*)&g_h2[(size_t)n * CO];
    const float4* sv = (const float4*)ss;
    const float4* dv = (const float4*)sd;
    float s = 0.f, d = 0.f;
#pragma unroll
    for (int q = 0; q < CO / 4; q++) {
        float4 hh = hv[q], a = sv[q], b = dv[q];
        s += hh.x * a.x + hh.y * a.y + hh.z * a.z + hh.w * a.w;
        d += hh.x * b.x + hh.y * b.y + hh.z * b.z + hh.w * b.w;
    }
    g_asrc2[n] = s;
    g_adst2[n] = d;
}

// ---------------- layer-1: fused softmax+aggregate (LDG.64 fp16, x2 unroll) ---
__global__ void __launch_bounds__(256) k_l1(const float* __restrict__ b1) {
    __shared__ float4 sal[8][64];
    int w = (blockIdx.x * blockDim.x + threadIdx.x) >> 5;
    if (w >= NNODES) return;
    const int n = w, lane = threadIdx.x & 31, ws = (threadIdx.x >> 5);
    const int beg = g_rowptr[n], end = g_rowptr[n + 1];
    const int deg = end - beg;
    const float4 ad = *(const float4*)&g_adst1[n * 4];
    const int h = lane >> 3;
    float4 acc = make_float4(0, 0, 0, 0);

    if (deg <= 64) {
        int s0 = 0, s1 = 0;
        float4 e0 = make_float4(0, 0, 0, 0), e1 = e0;
        const int p0 = beg + lane, p1 = p0 + 32;
        const bool v0 = p0 < end, v1 = p1 < end;
        float4 mx = make_float4(-CUDART_INF_F, -CUDART_INF_F,
                                -CUDART_INF_F, -CUDART_INF_F);
        if (v0) {
            s0 = g_csrc[p0];
            e0 = lrelu4(make_float4(g_asrc1[s0 * 4 + 0] + ad.x,
                                    g_asrc1[s0 * 4 + 1] + ad.y,
                                    g_asrc1[s0 * 4 + 2] + ad.z,
                                    g_asrc1[s0 * 4 + 3] + ad.w));
            mx = max4(mx, e0);
        }
        if (v1) {
            s1 = g_csrc[p1];
            e1 = lrelu4(make_float4(g_asrc1[s1 * 4 + 0] + ad.x,
                                    g_asrc1[s1 * 4 + 1] + ad.y,
                                    g_asrc1[s1 * 4 + 2] + ad.z,
                                    g_asrc1[s1 * 4 + 3] + ad.w));
            mx = max4(mx, e1);
        }
        mx = wred_max4(mx);
        float4 sm = make_float4(0, 0, 0, 0);
        float4 x0 = make_float4(0, 0, 0, 0), x1 = x0;
        if (v0) { x0 = exp4(e0, mx); sm.x += x0.x; sm.y += x0.y; sm.z += x0.z; sm.w += x0.w; }
        if (v1) { x1 = exp4(e1, mx); sm.x += x1.x; sm.y += x1.y; sm.z += x1.z; sm.w += x1.w; }
        sm = wred_sum4(sm);
        float4 inv = make_float4(1.f / (sm.x + EPSV), 1.f / (sm.y + EPSV),
                                 1.f / (sm.z + EPSV), 1.f / (sm.w + EPSV));
        if (v0) sal[ws][lane] = make_float4(x0.x * inv.x, x0.y * inv.y,
                                            x0.z * inv.z, x0.w * inv.w);
        if (v1) sal[ws][lane + 32] = make_float4(x1.x * inv.x, x1.y * inv.y,
                                                 x1.z * inv.z, x1.w * inv.w);
        __syncwarp();
        int j = 0;
        for (; j + 2 <= deg; j += 2) {
            int sa = __shfl_sync(0xffffffffu, (j < 32) ? s0 : s1, j & 31);
            int sb = __shfl_sync(0xffffffffu, (j + 1 < 32) ? s0 : s1, (j + 1) & 31);
            float aA = ((const float*)&sal[ws][j])[h];
            float aB = ((const float*)&sal[ws][j + 1])[h];
            float4 ha = ld_h4(&g_h1h[(size_t)sa * F1 + lane * 4]);
            float4 hb = ld_h4(&g_h1h[(size_t)sb * F1 + lane * 4]);
            acc.x = fmaf(ha.x, aA, acc.x); acc.y = fmaf(ha.y, aA, acc.y);
            acc.z = fmaf(ha.z, aA, acc.z); acc.w = fmaf(ha.w, aA, acc.w);
            acc.x = fmaf(hb.x, aB, acc.x); acc.y = fmaf(hb.y, aB, acc.y);
            acc.z = fmaf(hb.z, aB, acc.z); acc.w = fmaf(hb.w, aB, acc.w);
        }
        if (j < deg) {
            int sa = __shfl_sync(0xffffffffu, (j < 32) ? s0 : s1, j & 31);
            float aA = ((const float*)&sal[ws][j])[h];
            float4 ha = ld_h4(&g_h1h[(size_t)sa * F1 + lane * 4]);
            acc.x = fmaf(ha.x, aA, acc.x); acc.y = fmaf(ha.y, aA, acc.y);
            acc.z = fmaf(ha.z, aA, acc.z); acc.w = fmaf(ha.w, aA, acc.w);
        }
    } else {
        float4 mx = make_float4(-CUDART_INF_F, -CUDART_INF_F,
                                -CUDART_INF_F, -CUDART_INF_F);
        for (int p = beg + lane; p < end; p += 32) {
            int s = g_csrc[p];
            float4 e = lrelu4(make_float4(g_asrc1[s * 4 + 0] + ad.x,
                                          g_asrc1[s * 4 + 1] + ad.y,
                                          g_asrc1[s * 4 + 2] + ad.z,
                                          g_asrc1[s * 4 + 3] + ad.w));
            *(float4*)&g_ex1[(size_t)p * 4] = e;
            mx = max4(mx, e);
        }
        mx = wred_max4(mx);
        float4 sm = make_float4(0, 0, 0, 0);
        for (int p = beg + lane; p < end; p += 32) {
            float4 e = *(const float4*)&g_ex1[(size_t)p * 4];
            float4 ex = exp4(e, mx);
            *(float4*)&g_ex1[(size_t)p * 4] = ex;
            sm.x += ex.x; sm.y += ex.y; sm.z += ex.z; sm.w += ex.w;
        }
        sm = wred_sum4(sm);
        float4 inv = make_float4(1.f / (sm.x + EPSV), 1.f / (sm.y + EPSV),
                                 1.f / (sm.z + EPSV), 1.f / (sm.w + EPSV));
        __syncwarp();
        const float invh = (h == 0) ? inv.x : (h == 1) ? inv.y
                         : (h == 2) ? inv.z : inv.w;
        for (int p = beg; p < end; ++p) {
            int s = g_csrc[p];
            float alpha = g_ex1[(size_t)p * 4 + h] * invh;
            float4 ha = ld_h4(&g_h1h[(size_t)s * F1 + lane * 4]);
            acc.x = fmaf(ha.x, alpha, acc.x);
            acc.y = fmaf(ha.y, alpha, acc.y);
            acc.z = fmaf(ha.z, alpha, acc.z);
            acc.w = fmaf(ha.w, alpha, acc.w);
        }
    }

    float4 b = *(const float4*)&b1[lane * 4];
    float4 v = make_float4(acc.x + b.x, acc.y + b.y, acc.z + b.z, acc.w + b.w);
    v.x = v.x > 0.f ? v.x : expm1f(v.x);
    v.y = v.y > 0.f ? v.y : expm1f(v.y);
    v.z = v.z > 0.f ? v.z : expm1f(v.z);
    v.w = v.w > 0.f ? v.w : expm1f(v.w);
    *(float4*)&g_agg1[(size_t)n * F1 + lane * 4] = v;
}

// ---------------- layer-2: fused softmax+aggregate (LDG.32 fp16) + deg zero ---
#define GW2 ((NNODES * 32 + 255) / 256)     // 12500 main blocks
#define ZB2 ((NNODES + 255) / 256)          // 391 zeroing blocks

__global__ void __launch_bounds__(256) k_l2(const float* __restrict__ b2,
                                            float* __restrict__ out) {
    if (blockIdx.x >= GW2) {
        int i = (blockIdx.x - GW2) * 256 + threadIdx.x;
        if (i < NNODES) g_deg[i] = 0;    // restore invariant for next replay
        return;
    }
    __shared__ float sal[8][64];
    int w = (blockIdx.x * blockDim.x + threadIdx.x) >> 5;
    if (w >= NNODES) return;
    const int n = w, lane = threadIdx.x & 31, ws = (threadIdx.x >> 5);
    const int beg = g_rowptr[n], end = g_rowptr[n + 1];
    const int deg = end - beg;
    const float adn = g_adst2[n];
    float2 acc = make_float2(0, 0);

    if (deg <= 64) {
        int s0 = 0, s1 = 0;
        float e0 = 0.f, e1 = 0.f;
        const int p0 = beg + lane, p1 = p0 + 32;
        const bool v0 = p0 < end, v1 = p1 < end;
        float mx = -CUDART_INF_F;
        if (v0) { s0 = g_csrc[p0]; e0 = lrelu(g_asrc2[s0] + adn); mx = fmaxf(mx, e0); }
        if (v1) { s1 = g_csrc[p1]; e1 = lrelu(g_asrc2[s1] + adn); mx = fmaxf(mx, e1); }
#pragma unroll
        for (int o = 16; o > 0; o >>= 1)
            mx = fmaxf(mx, __shfl_xor_sync(0xffffffffu, mx, o));
        float sm = 0.f, x0 = 0.f, x1 = 0.f;
        if (v0) { x0 = __expf(e0 - mx); sm += x0; }
        if (v1) { x1 = __expf(e1 - mx); sm += x1; }
#pragma unroll
        for (int o = 16; o > 0; o >>= 1) sm += __shfl_xor_sync(0xffffffffu, sm, o);
        float inv = 1.f / (sm + EPSV);
        if (v0) sal[ws][lane]      = x0 * inv;
        if (v1) sal[ws][lane + 32] = x1 * inv;
        __syncwarp();
        int j = 0;
        for (; j + 2 <= deg; j += 2) {
            int sa = __shfl_sync(0xffffffffu, (j < 32) ? s0 : s1, j & 31);
            int sb = __shfl_sync(0xffffffffu, (j + 1 < 32) ? s0 : s1, (j + 1) & 31);
            float aA = sal[ws][j], aB = sal[ws][j + 1];
            float2 ha = ld_h2(&g_h2h[(size_t)sa * CO + lane * 2]);
            float2 hb = ld_h2(&g_h2h[(size_t)sb * CO + lane * 2]);
            acc.x = fmaf(ha.x, aA, acc.x); acc.y = fmaf(ha.y, aA, acc.y);
            acc.x = fmaf(hb.x, aB, acc.x); acc.y = fmaf(hb.y, aB, acc.y);
        }
        if (j < deg) {
            int sa = __shfl_sync(0xffffffffu, (j < 32) ? s0 : s1, j & 31);
            float aA = sal[ws][j];
            float2 ha = ld_h2(&g_h2h[(size_t)sa * CO + lane * 2]);
            acc.x = fmaf(ha.x, aA, acc.x); acc.y = fmaf(ha.y, aA, acc.y);
        }
    } else {
        float mx = -CUDART_INF_F;
        for (int p = beg + lane; p < end; p += 32) {
            int s = g_csrc[p];
            float e = lrelu(g_asrc2[s] + adn);
            g_ex2[p] = e;
            mx = fmaxf(mx, e);
        }
#pragma unroll
        for (int o = 16; o > 0; o >>= 1)
            mx = fmaxf(mx, __shfl_xor_sync(0xffffffffu, mx, o));
        float sm = 0.f;
        for (int p = beg + lane; p < end; p += 32) {
            float ex = __expf(g_ex2[p] - mx);
            g_ex2[p] = ex;
            sm += ex;
        }
#pragma unroll
        for (int o = 16; o > 0; o >>= 1) sm += __shfl_xor_sync(0xffffffffu, sm, o);
        float inv = 1.f / (sm + EPSV);
        __syncwarp();
        for (int p = beg; p < end; ++p) {
            int s = g_csrc[p];
            float alpha = g_ex2[p] * inv;
            float2 ha = ld_h2(&g_h2h[(size_t)s * CO + lane * 2]);
            acc.x = fmaf(ha.x, alpha, acc.x);
            acc.y = fmaf(ha.y, alpha, acc.y);
        }
    }

    float2 b = *(const float2*)&b2[lane * 2];
    *(float2*)&out[(size_t)n * CO + lane * 2] = make_float2(acc.x + b.x, acc.y + b.y);
}

// ---------------- launcher -------------------------------------------------------
extern "C" void kernel_launch(void* const* d_in, const int* in_sizes, int n_in,
                              void* d_out, int out_size) {
    const float* x   = (const float*)d_in[0];
    const void*  ei  = d_in[1];
    const float* W1  = (const float*)d_in[2];
    const float* as1 = (const float*)d_in[3];
    const float* ad1 = (const float*)d_in[4];
    const float* b1  = (const float*)d_in[5];
    const float* W2  = (const float*)d_in[6];
    const float* as2 = (const float*)d_in[7];
    const float* ad2 = (const float*)d_in[8];
    const float* b2  = (const float*)d_in[9];
    float* out = (float*)d_out;

    (void)in_sizes; (void)n_in; (void)out_size;

    const int gNode = (NNODES + TPB - 1) / TPB;
    const int gEdge = (ETOT + TPB - 1) / TPB;

    k_gemm1_prep<<<GB1 + PB, 256>>>(x, W1, ei);      // 0
    k_att1_scan1<<<AB1 + NB1, SCAN_B>>>(as1, ad1);   // 1
    k_scan23<<<NB1, SCAN_B>>>();                     // 2
    k_scatter<<<gEdge, TPB>>>();                     // 3  <- profiler capture
    k_l1<<<GW2, TPB>>>(b1);                          // 4
    gemm2_kernel<<<(NNODES + 127) / 128, 256>>>(W2); // 5
    k_att2<<<gNode, TPB>>>(as2, ad2);                // 6
    k_l2<<<GW2 + ZB2, TPB>>>(b2, out);               // 7
}

// round 15
// speedup vs baseline: 1.1196x; 1.0981x over previous
#include <cuda_runtime.h>
#include <cuda_fp16.h>
#include <math_constants.h>

// ---------------------------------------------------------------------------
// GAT 2-layer forward, fixed shapes. CSR-based, zero float atomics.
// R15: att1/att2 fused into GEMM epilogues; decoupled-lookback single-kernel
//      scan; prep reads dst only (scatter re-decodes); 6-launch pipeline with
//      k_l1 at profiler capture index 3.
// ---------------------------------------------------------------------------

#define NNODES 100000
#define E_IN   1600000
#define ETOT   (E_IN + NNODES)
#define NH1    4
#define F1     128
#define FIN    256
#define CO     64
#define EPSV   1e-16f
#define SCAN_B 512
#define NB1    ((NNODES + SCAN_B - 1) / SCAN_B)   // 196

static const int TPB = 256;

// ---------------- device scratch (static, 16B-aligned) ----------------------
__device__ __align__(16) float  g_h1  [(size_t)NNODES * F1];
__device__ __align__(16) __half g_h1h [(size_t)NNODES * F1];
__device__ __align__(16) float  g_agg1[(size_t)NNODES * F1];
__device__ __align__(16) float  g_h2  [(size_t)NNODES * CO];
__device__ __align__(16) __half g_h2h [(size_t)NNODES * CO];
__device__ __align__(16) float  g_asrc1[NNODES * NH1];
__device__ __align__(16) float  g_adst1[NNODES * NH1];
__device__ __align__(16) float  g_ex1 [(size_t)ETOT * NH1];   // deg>64 fallback
__device__ __align__(16) float  g_asrc2[NNODES];
__device__ __align__(16) float  g_adst2[NNODES];
__device__ __align__(16) float  g_ex2 [ETOT];                 // deg>64 fallback
// CSR machinery (g_deg / g_state zero-init static; re-zeroed by k_l2 tail)
__device__ int      g_csrc[ETOT];
__device__ int      g_deg [NNODES];
__device__ unsigned g_state[NB1];          // lookback scan state
__device__ int      g_rowptr[NNODES + 1];
__device__ int      g_wcur[NNODES];

// ---------------- helpers ----------------------------------------------------
__device__ __forceinline__ float lrelu(float v) { return v >= 0.f ? v : 0.2f * v; }
__device__ __forceinline__ float4 lrelu4(float4 v) {
    return make_float4(lrelu(v.x), lrelu(v.y), lrelu(v.z), lrelu(v.w));
}
__device__ __forceinline__ float4 max4(float4 a, float4 b) {
    return make_float4(fmaxf(a.x, b.x), fmaxf(a.y, b.y),
                       fmaxf(a.z, b.z), fmaxf(a.w, b.w));
}
__device__ __forceinline__ float4 exp4(float4 a, float4 m) {
    return make_float4(__expf(a.x - m.x), __expf(a.y - m.y),
                       __expf(a.z - m.z), __expf(a.w - m.w));
}
__device__ __forceinline__ float4 wred_max4(float4 v) {
#pragma unroll
    for (int o = 16; o > 0; o >>= 1) {
        v.x = fmaxf(v.x, __shfl_xor_sync(0xffffffffu, v.x, o));
        v.y = fmaxf(v.y, __shfl_xor_sync(0xffffffffu, v.y, o));
        v.z = fmaxf(v.z, __shfl_xor_sync(0xffffffffu, v.z, o));
        v.w = fmaxf(v.w, __shfl_xor_sync(0xffffffffu, v.w, o));
    }
    return v;
}
__device__ __forceinline__ float4 wred_sum4(float4 v) {
#pragma unroll
    for (int o = 16; o > 0; o >>= 1) {
        v.x += __shfl_xor_sync(0xffffffffu, v.x, o);
        v.y += __shfl_xor_sync(0xffffffffu, v.y, o);
        v.z += __shfl_xor_sync(0xffffffffu, v.z, o);
        v.w += __shfl_xor_sync(0xffffffffu, v.w, o);
    }
    return v;
}
__device__ __forceinline__ float red4(float v) {
    v += __shfl_xor_sync(0xffffffffu, v, 1);
    v += __shfl_xor_sync(0xffffffffu, v, 2);
    return v;
}
__device__ __forceinline__ unsigned f2tf32(float f) {
    unsigned u;
    asm("cvt.rna.tf32.f32 %0, %1;" : "=r"(u) : "f"(f));
    return u;
}
__device__ __forceinline__ void mma_tf32(float4& d, const unsigned a[4],
                                         unsigned b0, unsigned b1) {
    asm volatile(
        "mma.sync.aligned.m16n8k8.row.col.f32.tf32.tf32.f32 "
        "{%0,%1,%2,%3}, {%4,%5,%6,%7}, {%8,%9}, {%0,%1,%2,%3};\n"
        : "+f"(d.x), "+f"(d.y), "+f"(d.z), "+f"(d.w)
        : "r"(a[0]), "r"(a[1]), "r"(a[2]), "r"(a[3]), "r"(b0), "r"(b1));
}
__device__ __forceinline__ float4 ld_h4(const __half* p) {
    float2 raw = *(const float2*)p;
    __half2 p0 = *(__half2*)&raw.x;
    __half2 p1 = *(__half2*)&raw.y;
    float2 f0 = __half22float2(p0), f1 = __half22float2(p1);
    return make_float4(f0.x, f0.y, f1.x, f1.y);
}
__device__ __forceinline__ float2 ld_h2(const __half* p) {
    float raw = *(const float*)p;
    return __half22float2(*(__half2*)&raw);
}
// dtype-robust edge decode (int64 declared, int32 likely under JAX x64=off)
__device__ __forceinline__ bool edge_is64(const void* ei_raw) {
    const long long* e64 = (const long long*)ei_raw;
    bool is64 = true;
#pragma unroll
    for (int q = 0; q < 4; q++) {
        long long v = e64[q];
        if (v < 0 || v >= NNODES) is64 = false;
    }
    return is64;
}

// ---------------- fused: gemm1 (tf32 HMMA) + att1 epilogue || dst histogram ---
#define GB1 ((NNODES + 127) / 128)          // 782 gemm blocks
#define PB  ((ETOT + 255) / 256)            // 6641 histogram blocks

__global__ void __launch_bounds__(256) k_gemm1_prep(const float* __restrict__ A,
                                                    const float* __restrict__ B,
                                                    const void* __restrict__ ei_raw,
                                                    const float* __restrict__ att_s,
                                                    const float* __restrict__ att_d) {
    __shared__ unsigned As[128][36];
    __shared__ unsigned Bs[32][136];
    __shared__ float    s_as[F1], s_ad[F1];

    if (blockIdx.x >= GB1) {
        // ---- histogram of destinations only ----
        int e = (blockIdx.x - GB1) * 256 + threadIdx.x;
        if (e >= ETOT) return;
        int d;
        if (e >= E_IN) {
            d = e - E_IN;
        } else if (edge_is64(ei_raw)) {
            d = (int)((const long long*)ei_raw)[(size_t)E_IN + e];
        } else {
            d = ((const int*)ei_raw)[E_IN + e];
        }
        atomicAdd(&g_deg[d], 1);
        return;
    }

    const int tid  = threadIdx.x;
    const int lane = tid & 31, wid = tid >> 5;
    const int wm = (wid & 3) * 32;
    const int wn = (wid >> 2) * 64;
    const int row0 = blockIdx.x * 128;
    const int g = lane >> 2, tg = lane & 3;

    if (tid < F1) { s_as[tid] = att_s[tid]; s_ad[tid] = att_d[tid]; }

    float4 acc[2][8];
#pragma unroll
    for (int mt = 0; mt < 2; mt++)
#pragma unroll
        for (int nt = 0; nt < 8; nt++) acc[mt][nt] = make_float4(0, 0, 0, 0);

    for (int k0 = 0; k0 < FIN; k0 += 32) {
#pragma unroll
        for (int q = 0; q < 4; q++) {
            int f4 = tid + q * 256;
            int r = f4 >> 3, c = (f4 & 7) * 4;
            float4 v = make_float4(0, 0, 0, 0);
            int gr = row0 + r;
            if (gr < NNODES) v = *(const float4*)&A[(size_t)gr * FIN + k0 + c];
            *(uint4*)&As[r][c] =
                make_uint4(f2tf32(v.x), f2tf32(v.y), f2tf32(v.z), f2tf32(v.w));
        }
#pragma unroll
        for (int q = 0; q < 4; q++) {
            int f4 = tid + q * 256;
            int r = f4 >> 5, c = (f4 & 31) * 4;
            float4 v = *(const float4*)&B[(size_t)(k0 + r) * F1 + c];
            *(uint4*)&Bs[r][c] =
                make_uint4(f2tf32(v.x), f2tf32(v.y), f2tf32(v.z), f2tf32(v.w));
        }
        __syncthreads();

#pragma unroll
        for (int kk = 0; kk < 32; kk += 8) {
            unsigned a[2][4];
#pragma unroll
            for (int mt = 0; mt < 2; mt++) {
                int rb = wm + mt * 16;
                a[mt][0] = As[rb + g][kk + tg];
                a[mt][1] = As[rb + 8 + g][kk + tg];
                a[mt][2] = As[rb + g][kk + tg + 4];
                a[mt][3] = As[rb + 8 + g][kk + tg + 4];
            }
#pragma unroll
            for (int nt = 0; nt < 8; nt++) {
                unsigned b0 = Bs[kk + tg][wn + nt * 8 + g];
                unsigned b1 = Bs[kk + 4 + tg][wn + nt * 8 + g];
                mma_tf32(acc[0][nt], a[0], b0, b1);
                mma_tf32(acc[1][nt], a[1], b0, b1);
            }
        }
        __syncthreads();
    }

    // ---- store h1 fp32 + fp16 shadow ----
#pragma unroll
    for (int mt = 0; mt < 2; mt++) {
#pragma unroll
        for (int nt = 0; nt < 8; nt++) {
            int r = row0 + wm + mt * 16 + g;
            int c = wn + nt * 8 + tg * 2;
            if (r < NNODES) {
                *(float2*)&g_h1[(size_t)r * F1 + c] =
                    make_float2(acc[mt][nt].x, acc[mt][nt].y);
                *(__half2*)&g_h1h[(size_t)r * F1 + c] =
                    __floats2half2_rn(acc[mt][nt].x, acc[mt][nt].y);
            }
            if (r + 8 < NNODES) {
                *(float2*)&g_h1[(size_t)(r + 8) * F1 + c] =
                    make_float2(acc[mt][nt].z, acc[mt][nt].w);
                *(__half2*)&g_h1h[(size_t)(r + 8) * F1 + c] =
                    __floats2half2_rn(acc[mt][nt].z, acc[mt][nt].w);
            }
        }
    }

    // ---- att1 epilogue: per-row dot with att_src/att_dst, heads hb, hb+1 ----
    float ps[2][2][2] = {{{0}}}, pd[2][2][2] = {{{0}}};
#pragma unroll
    for (int mt = 0; mt < 2; mt++)
#pragma unroll
        for (int nt = 0; nt < 8; nt++) {
            int c = wn + nt * 8 + tg * 2;
            int hl = nt >> 2;
            float a0s = s_as[c], a1s = s_as[c + 1];
            float a0d = s_ad[c], a1d = s_ad[c + 1];
            float4 v = acc[mt][nt];
            ps[mt][0][hl] += v.x * a0s + v.y * a1s;
            pd[mt][0][hl] += v.x * a0d + v.y * a1d;
            ps[mt][1][hl] += v.z * a0s + v.w * a1s;
            pd[mt][1][hl] += v.z * a0d + v.w * a1d;
        }
#pragma unroll
    for (int mt = 0; mt < 2; mt++)
#pragma unroll
        for (int rh = 0; rh < 2; rh++)
#pragma unroll
            for (int hl = 0; hl < 2; hl++) {
                ps[mt][rh][hl] = red4(ps[mt][rh][hl]);
                pd[mt][rh][hl] = red4(pd[mt][rh][hl]);
            }
    if (tg == 0) {
        int hb = wn >> 5;   // 0 for cols 0-63 (heads 0,1); 2 for cols 64-127
#pragma unroll
        for (int mt = 0; mt < 2; mt++)
#pragma unroll
            for (int rh = 0; rh < 2; rh++) {
                int r = row0 + wm + mt * 16 + g + rh * 8;
                if (r < NNODES) {
                    g_asrc1[r * 4 + hb]     = ps[mt][rh][0];
                    g_asrc1[r * 4 + hb + 1] = ps[mt][rh][1];
                    g_adst1[r * 4 + hb]     = pd[mt][rh][0];
                    g_adst1[r * 4 + hb + 1] = pd[mt][rh][1];
                }
            }
    }
}

// ---------------- single-kernel decoupled-lookback scan -----------------------
#define FLAG_AGG 0x40000000u
#define FLAG_PRE 0x80000000u
#define VAL_MASK 0x3FFFFFFFu

__global__ void __launch_bounds__(SCAN_B) k_scan() {
    const int t = threadIdx.x, b = blockIdx.x;
    const int i = b * SCAN_B + t;
    const int deg_i = (i < NNODES) ? g_deg[i] : 0;
    int lane = t & 31, wid = t >> 5;
    int v = deg_i;
#pragma unroll
    for (int o = 1; o < 32; o <<= 1) {
        int u = __shfl_up_sync(0xffffffffu, v, o);
        if (lane >= o) v += u;
    }
    __shared__ int wsum[SCAN_B / 32];
    if (lane == 31) wsum[wid] = v;
    __syncthreads();
    if (wid == 0) {
        int w = (lane < SCAN_B / 32) ? wsum[lane] : 0;
#pragma unroll
        for (int o = 1; o < 32; o <<= 1) {
            int u = __shfl_up_sync(0xffffffffu, w, o);
            if (lane >= o) w += u;
        }
        if (lane < SCAN_B / 32) wsum[lane] = w;
    }
    __syncthreads();
    int incl = v + (wid ? wsum[wid - 1] : 0);

    __shared__ int s_total, s_excl;
    if (t == SCAN_B - 1) s_total = incl;
    __syncthreads();
    const int total = s_total;

    if (wid == 0) {
        if (b == 0) {
            if (lane == 0) {
                atomicExch(&g_state[0], FLAG_PRE | (unsigned)total);
                s_excl = 0;
            }
        } else {
            if (lane == 0) atomicExch(&g_state[b], FLAG_AGG | (unsigned)total);
            int idx = b - 1, excl = 0;
            for (;;) {
                int j = idx - lane;
                unsigned s = 0;
                if (j >= 0) {
                    do { s = *(volatile unsigned*)&g_state[j]; }
                    while (!(s & (FLAG_AGG | FLAG_PRE)));
                }
                unsigned pf = __ballot_sync(0xffffffffu, j >= 0 && (s & FLAG_PRE));
                if (pf) {
                    int cut = __ffs(pf) - 1;   // closest block with full prefix
                    int contrib = (j >= 0 && lane <= cut) ? (int)(s & VAL_MASK) : 0;
#pragma unroll
                    for (int o = 16; o > 0; o >>= 1)
                        contrib += __shfl_xor_sync(0xffffffffu, contrib, o);
                    excl += contrib;
                    break;
                }
                int contrib = (j >= 0) ? (int)(s & VAL_MASK) : 0;
#pragma unroll
                for (int o = 16; o > 0; o >>= 1)
                    contrib += __shfl_xor_sync(0xffffffffu, contrib, o);
                excl += contrib;
                idx -= 32;
                if (idx < 0) break;   // unreachable (block 0 publishes PREFIX)
            }
            if (lane == 0) {
                atomicExch(&g_state[b], FLAG_PRE | (unsigned)(excl + total));
                s_excl = excl;
            }
        }
    }
    __syncthreads();

    if (i < NNODES) {
        int e = s_excl + incl - deg_i;
        g_rowptr[i] = e;
        g_wcur[i]   = e;
    }
    if (b == 0 && t == 0) g_rowptr[NNODES] = ETOT;
}

// ---------------- scatter: decode + CSR fill (2 edges/thread) -----------------
__global__ void k_scatter(const void* __restrict__ ei_raw) {
    int base = (blockIdx.x * blockDim.x + threadIdx.x) * 2;
    if (base >= ETOT) return;
    bool is64 = edge_is64(ei_raw);
#pragma unroll
    for (int q = 0; q < 2; q++) {
        int e = base + q;
        if (e >= ETOT) break;
        int s, d;
        if (e >= E_IN) {
            s = d = e - E_IN;
        } else if (is64) {
            const long long* e64 = (const long long*)ei_raw;
            s = (int)e64[e];
            d = (int)e64[(size_t)E_IN + e];
        } else {
            const int* e32 = (const int*)ei_raw;
            s = e32[e];
            d = e32[E_IN + e];
        }
        int pos = atomicAdd(&g_wcur[d], 1);
        g_csrc[pos] = s;
    }
}

// ---------------- gemm2 (tf32 HMMA) + att2 epilogue ---------------------------
__global__ void __launch_bounds__(256) k_gemm2(const float* __restrict__ B,
                                               const float* __restrict__ att_s,
                                               const float* __restrict__ att_d) {
    __shared__ unsigned As[128][36];
    __shared__ unsigned Bs[32][72];
    __shared__ float s2s[CO], s2d[CO];
    __shared__ float sps[2][128], spd[2][128];
    const float* A = g_agg1;
    const int tid  = threadIdx.x;
    const int lane = tid & 31, wid = tid >> 5;
    const int wm = (wid & 3) * 32;
    const int wn = (wid >> 2) * 32;
    const int row0 = blockIdx.x * 128;
    const int g = lane >> 2, tg = lane & 3;

    if (tid < CO) { s2s[tid] = att_s[tid]; s2d[tid] = att_d[tid]; }

    float4 acc[2][4];
#pragma unroll
    for (int mt = 0; mt < 2; mt++)
#pragma unroll
        for (int nt = 0; nt < 4; nt++) acc[mt][nt] = make_float4(0, 0, 0, 0);

    for (int k0 = 0; k0 < F1; k0 += 32) {
#pragma unroll
        for (int q = 0; q < 4; q++) {
            int f4 = tid + q * 256;
            int r = f4 >> 3, c = (f4 & 7) * 4;
            float4 v = make_float4(0, 0, 0, 0);
            int gr = row0 + r;
            if (gr < NNODES) v = *(const float4*)&A[(size_t)gr * F1 + k0 + c];
            *(uint4*)&As[r][c] =
                make_uint4(f2tf32(v.x), f2tf32(v.y), f2tf32(v.z), f2tf32(v.w));
        }
#pragma unroll
        for (int q = 0; q < 2; q++) {
            int f4 = tid + q * 256;
            int r = f4 >> 4, c = (f4 & 15) * 4;
            float4 v = *(const float4*)&B[(size_t)(k0 + r) * CO + c];
            *(uint4*)&Bs[r][c] =
                make_uint4(f2tf32(v.x), f2tf32(v.y), f2tf32(v.z), f2tf32(v.w));
        }
        __syncthreads();

#pragma unroll
        for (int kk = 0; kk < 32; kk += 8) {
            unsigned a[2][4];
#pragma unroll
            for (int mt = 0; mt < 2; mt++) {
                int rb = wm + mt * 16;
                a[mt][0] = As[rb + g][kk + tg];
                a[mt][1] = As[rb + 8 + g][kk + tg];
                a[mt][2] = As[rb + g][kk + tg + 4];
                a[mt][3] = As[rb + 8 + g][kk + tg + 4];
            }
#pragma unroll
            for (int nt = 0; nt < 4; nt++) {
                unsigned b0 = Bs[kk + tg][wn + nt * 8 + g];
                unsigned b1 = Bs[kk + 4 + tg][wn + nt * 8 + g];
                mma_tf32(acc[0][nt], a[0], b0, b1);
                mma_tf32(acc[1][nt], a[1], b0, b1);
            }
        }
        __syncthreads();
    }

#pragma unroll
    for (int mt = 0; mt < 2; mt++) {
#pragma unroll
        for (int nt = 0; nt < 4; nt++) {
            int r = row0 + wm + mt * 16 + g;
            int c = wn + nt * 8 + tg * 2;
            if (r < NNODES) {
                *(float2*)&g_h2[(size_t)r * CO + c] =
                    make_float2(acc[mt][nt].x, acc[mt][nt].y);
                *(__half2*)&g_h2h[(size_t)r * CO + c] =
                    __floats2half2_rn(acc[mt][nt].x, acc[mt][nt].y);
            }
            if (r + 8 < NNODES) {
                *(float2*)&g_h2[(size_t)(r + 8) * CO + c] =
                    make_float2(acc[mt][nt].z, acc[mt][nt].w);
                *(__half2*)&g_h2h[(size_t)(r + 8) * CO + c] =
                    __floats2half2_rn(acc[mt][nt].z, acc[mt][nt].w);
            }
        }
    }

    // ---- att2 epilogue: single head spans both 32-col warp halves ----
    float ps[2][2] = {{0}}, pd[2][2] = {{0}};
#pragma unroll
    for (int mt = 0; mt < 2; mt++)
#pragma unroll
        for (int nt = 0; nt < 4; nt++) {
            int c = wn + nt * 8 + tg * 2;
            float4 v = acc[mt][nt];
            ps[mt][0] += v.x * s2s[c] + v.y * s2s[c + 1];
            pd[mt][0] += v.x * s2d[c] + v.y * s2d[c + 1];
            ps[mt][1] += v.z * s2s[c] + v.w * s2s[c + 1];
            pd[mt][1] += v.z * s2d[c] + v.w * s2d[c + 1];
        }
#pragma unroll
    for (int mt = 0; mt < 2; mt++)
#pragma unroll
        for (int rh = 0; rh < 2; rh++) {
            ps[mt][rh] = red4(ps[mt][rh]);
            pd[mt][rh] = red4(pd[mt][rh]);
        }
    if (tg == 0) {
        int half = wn >> 5;
#pragma unroll
        for (int mt = 0; mt < 2; mt++)
#pragma unroll
            for (int rh = 0; rh < 2; rh++) {
                int rl = wm + mt * 16 + g + rh * 8;
                sps[half][rl] = ps[mt][rh];
                spd[half][rl] = pd[mt][rh];
            }
    }
    __syncthreads();
    if (tid < 128) {
        int r = row0 + tid;
        if (r < NNODES) {
            g_asrc2[r] = sps[0][tid] + sps[1][tid];
            g_adst2[r] = spd[0][tid] + spd[1][tid];
        }
    }
}

// ---------------- layer-1: fused softmax+aggregate ----------------------------
__global__ void __launch_bounds__(256) k_l1(const float* __restrict__ b1) {
    __shared__ float4 sal[8][64];
    int w = (blockIdx.x * blockDim.x + threadIdx.x) >> 5;
    if (w >= NNODES) return;
    const int n = w, lane = threadIdx.x & 31, ws = (threadIdx.x >> 5);
    const int beg = g_rowptr[n], end = g_rowptr[n + 1];
    const int deg = end - beg;
    const float4 ad = *(const float4*)&g_adst1[n * 4];
    const int h = lane >> 3;
    float4 acc = make_float4(0, 0, 0, 0);

    if (deg <= 64) {
        int s0 = 0, s1 = 0;
        float4 e0 = make_float4(0, 0, 0, 0), e1 = e0;
        const int p0 = beg + lane, p1 = p0 + 32;
        const bool v0 = p0 < end, v1 = p1 < end;
        float4 mx = make_float4(-CUDART_INF_F, -CUDART_INF_F,
                                -CUDART_INF_F, -CUDART_INF_F);
        if (v0) {
            s0 = g_csrc[p0];
            e0 = lrelu4(make_float4(g_asrc1[s0 * 4 + 0] + ad.x,
                                    g_asrc1[s0 * 4 + 1] + ad.y,
                                    g_asrc1[s0 * 4 + 2] + ad.z,
                                    g_asrc1[s0 * 4 + 3] + ad.w));
            mx = max4(mx, e0);
        }
        if (v1) {
            s1 = g_csrc[p1];
            e1 = lrelu4(make_float4(g_asrc1[s1 * 4 + 0] + ad.x,
                                    g_asrc1[s1 * 4 + 1] + ad.y,
                                    g_asrc1[s1 * 4 + 2] + ad.z,
                                    g_asrc1[s1 * 4 + 3] + ad.w));
            mx = max4(mx, e1);
        }
        mx = wred_max4(mx);
        float4 sm = make_float4(0, 0, 0, 0);
        float4 x0 = make_float4(0, 0, 0, 0), x1 = x0;
        if (v0) { x0 = exp4(e0, mx); sm.x += x0.x; sm.y += x0.y; sm.z += x0.z; sm.w += x0.w; }
        if (v1) { x1 = exp4(e1, mx); sm.x += x1.x; sm.y += x1.y; sm.z += x1.z; sm.w += x1.w; }
        sm = wred_sum4(sm);
        float4 inv = make_float4(1.f / (sm.x + EPSV), 1.f / (sm.y + EPSV),
                                 1.f / (sm.z + EPSV), 1.f / (sm.w + EPSV));
        if (v0) sal[ws][lane] = make_float4(x0.x * inv.x, x0.y * inv.y,
                                            x0.z * inv.z, x0.w * inv.w);
        if (v1) sal[ws][lane + 32] = make_float4(x1.x * inv.x, x1.y * inv.y,
                                                 x1.z * inv.z, x1.w * inv.w);
        __syncwarp();
        int j = 0;
        for (; j + 2 <= deg; j += 2) {
            int sa = __shfl_sync(0xffffffffu, (j < 32) ? s0 : s1, j & 31);
            int sb = __shfl_sync(0xffffffffu, (j + 1 < 32) ? s0 : s1, (j + 1) & 31);
            float aA = ((const float*)&sal[ws][j])[h];
            float aB = ((const float*)&sal[ws][j + 1])[h];
            float4 ha = ld_h4(&g_h1h[(size_t)sa * F1 + lane * 4]);
            float4 hb = ld_h4(&g_h1h[(size_t)sb * F1 + lane * 4]);
            acc.x = fmaf(ha.x, aA, acc.x); acc.y = fmaf(ha.y, aA, acc.y);
            acc.z = fmaf(ha.z, aA, acc.z); acc.w = fmaf(ha.w, aA, acc.w);
            acc.x = fmaf(hb.x, aB, acc.x); acc.y = fmaf(hb.y, aB, acc.y);
            acc.z = fmaf(hb.z, aB, acc.z); acc.w = fmaf(hb.w, aB, acc.w);
        }
        if (j < deg) {
            int sa = __shfl_sync(0xffffffffu, (j < 32) ? s0 : s1, j & 31);
            float aA = ((const float*)&sal[ws][j])[h];
            float4 ha = ld_h4(&g_h1h[(size_t)sa * F1 + lane * 4]);
            acc.x = fmaf(ha.x, aA, acc.x); acc.y = fmaf(ha.y, aA, acc.y);
            acc.z = fmaf(ha.z, aA, acc.z); acc.w = fmaf(ha.w, aA, acc.w);
        }
    } else {
        float4 mx = make_float4(-CUDART_INF_F, -CUDART_INF_F,
                                -CUDART_INF_F, -CUDART_INF_F);
        for (int p = beg + lane; p < end; p += 32) {
            int s = g_csrc[p];
            float4 e = lrelu4(make_float4(g_asrc1[s * 4 + 0] + ad.x,
                                          g_asrc1[s * 4 + 1] + ad.y,
                                          g_asrc1[s * 4 + 2] + ad.z,
                                          g_asrc1[s * 4 + 3] + ad.w));
            *(float4*)&g_ex1[(size_t)p * 4] = e;
            mx = max4(mx, e);
        }
        mx = wred_max4(mx);
        float4 sm = make_float4(0, 0, 0, 0);
        for (int p = beg + lane; p < end; p += 32) {
            float4 e = *(const float4*)&g_ex1[(size_t)p * 4];
            float4 ex = exp4(e, mx);
            *(float4*)&g_ex1[(size_t)p * 4] = ex;
            sm.x += ex.x; sm.y += ex.y; sm.z += ex.z; sm.w += ex.w;
        }
        sm = wred_sum4(sm);
        float4 inv = make_float4(1.f / (sm.x + EPSV), 1.f / (sm.y + EPSV),
                                 1.f / (sm.z + EPSV), 1.f / (sm.w + EPSV));
        __syncwarp();
        const float invh = (h == 0) ? inv.x : (h == 1) ? inv.y
                         : (h == 2) ? inv.z : inv.w;
        for (int p = beg; p < end; ++p) {
            int s = g_csrc[p];
            float alpha = g_ex1[(size_t)p * 4 + h] * invh;
            float4 ha = ld_h4(&g_h1h[(size_t)s * F1 + lane * 4]);
            acc.x = fmaf(ha.x, alpha, acc.x);
            acc.y = fmaf(ha.y, alpha, acc.y);
            acc.z = fmaf(ha.z, alpha, acc.z);
            acc.w = fmaf(ha.w, alpha, acc.w);
        }
    }

    float4 b = *(const float4*)&b1[lane * 4];
    float4 v = make_float4(acc.x + b.x, acc.y + b.y, acc.z + b.z, acc.w + b.w);
    v.x = v.x > 0.f ? v.x : expm1f(v.x);
    v.y = v.y > 0.f ? v.y : expm1f(v.y);
    v.z = v.z > 0.f ? v.z : expm1f(v.z);
    v.w = v.w > 0.f ? v.w : expm1f(v.w);
    *(float4*)&g_agg1[(size_t)n * F1 + lane * 4] = v;
}

// ---------------- layer-2: fused softmax+aggregate + state re-zero ------------
#define GW2 ((NNODES * 32 + 255) / 256)     // 12500 main blocks
#define ZB2 ((NNODES + 255) / 256)          // 391 zeroing blocks

__global__ void __launch_bounds__(256) k_l2(const float* __restrict__ b2,
                                            float* __restrict__ out) {
    if (blockIdx.x >= GW2) {
        int i = (blockIdx.x - GW2) * 256 + threadIdx.x;
        if (i < NNODES) g_deg[i] = 0;       // replay invariant
        if (i < NB1)    g_state[i] = 0;     // replay invariant
        return;
    }
    __shared__ float sal[8][64];
    int w = (blockIdx.x * blockDim.x + threadIdx.x) >> 5;
    if (w >= NNODES) return;
    const int n = w, lane = threadIdx.x & 31, ws = (threadIdx.x >> 5);
    const int beg = g_rowptr[n], end = g_rowptr[n + 1];
    const int deg = end - beg;
    const float adn = g_adst2[n];
    float2 acc = make_float2(0, 0);

    if (deg <= 64) {
        int s0 = 0, s1 = 0;
        float e0 = 0.f, e1 = 0.f;
        const int p0 = beg + lane, p1 = p0 + 32;
        const bool v0 = p0 < end, v1 = p1 < end;
        float mx = -CUDART_INF_F;
        if (v0) { s0 = g_csrc[p0]; e0 = lrelu(g_asrc2[s0] + adn); mx = fmaxf(mx, e0); }
        if (v1) { s1 = g_csrc[p1]; e1 = lrelu(g_asrc2[s1] + adn); mx = fmaxf(mx, e1); }
#pragma unroll
        for (int o = 16; o > 0; o >>= 1)
            mx = fmaxf(mx, __shfl_xor_sync(0xffffffffu, mx, o));
        float sm = 0.f, x0 = 0.f, x1 = 0.f;
        if (v0) { x0 = __expf(e0 - mx); sm += x0; }
        if (v1) { x1 = __expf(e1 - mx); sm += x1; }
#pragma unroll
        for (int o = 16; o > 0; o >>= 1) sm += __shfl_xor_sync(0xffffffffu, sm, o);
        float inv = 1.f / (sm + EPSV);
        if (v0) sal[ws][lane]      = x0 * inv;
        if (v1) sal[ws][lane + 32] = x1 * inv;
        __syncwarp();
        int j = 0;
        for (; j + 2 <= deg; j += 2) {
            int sa = __shfl_sync(0xffffffffu, (j < 32) ? s0 : s1, j & 31);
            int sb = __shfl_sync(0xffffffffu, (j + 1 < 32) ? s0 : s1, (j + 1) & 31);
            float aA = sal[ws][j], aB = sal[ws][j + 1];
            float2 ha = ld_h2(&g_h2h[(size_t)sa * CO + lane * 2]);
            float2 hb = ld_h2(&g_h2h[(size_t)sb * CO + lane * 2]);
            acc.x = fmaf(ha.x, aA, acc.x); acc.y = fmaf(ha.y, aA, acc.y);
            acc.x = fmaf(hb.x, aB, acc.x); acc.y = fmaf(hb.y, aB, acc.y);
        }
        if (j < deg) {
            int sa = __shfl_sync(0xffffffffu, (j < 32) ? s0 : s1, j & 31);
            float aA = sal[ws][j];
            float2 ha = ld_h2(&g_h2h[(size_t)sa * CO + lane * 2]);
            acc.x = fmaf(ha.x, aA, acc.x); acc.y = fmaf(ha.y, aA, acc.y);
        }
    } else {
        float mx = -CUDART_INF_F;
        for (int p = beg + lane; p < end; p += 32) {
            int s = g_csrc[p];
            float e = lrelu(g_asrc2[s] + adn);
            g_ex2[p] = e;
            mx = fmaxf(mx, e);
        }
#pragma unroll
        for (int o = 16; o > 0; o >>= 1)
            mx = fmaxf(mx, __shfl_xor_sync(0xffffffffu, mx, o));
        float sm = 0.f;
        for (int p = beg + lane; p < end; p += 32) {
            float ex = __expf(g_ex2[p] - mx);
            g_ex2[p] = ex;
            sm += ex;
        }
#pragma unroll
        for (int o = 16; o > 0; o >>= 1) sm += __shfl_xor_sync(0xffffffffu, sm, o);
        float inv = 1.f / (sm + EPSV);
        __syncwarp();
        for (int p = beg; p < end; ++p) {
            int s = g_csrc[p];
            float alpha = g_ex2[p] * inv;
            float2 ha = ld_h2(&g_h2h[(size_t)s * CO + lane * 2]);
            acc.x = fmaf(ha.x, alpha, acc.x);
            acc.y = fmaf(ha.y, alpha, acc.y);
        }
    }

    float2 b = *(const float2*)&b2[lane * 2];
    *(float2*)&out[(size_t)n * CO + lane * 2] = make_float2(acc.x + b.x, acc.y + b.y);
}

// ---------------- launcher -------------------------------------------------------
extern "C" void kernel_launch(void* const* d_in, const int* in_sizes, int n_in,
                              void* d_out, int out_size) {
    const float* x   = (const float*)d_in[0];
    const void*  ei  = d_in[1];
    const float* W1  = (const float*)d_in[2];
    const float* as1 = (const float*)d_in[3];
    const float* ad1 = (const float*)d_in[4];
    const float* b1  = (const float*)d_in[5];
    const float* W2  = (const float*)d_in[6];
    const float* as2 = (const float*)d_in[7];
    const float* ad2 = (const float*)d_in[8];
    const float* b2  = (const float*)d_in[9];
    float* out = (float*)d_out;

    (void)in_sizes; (void)n_in; (void)out_size;

    const int gScat = ((ETOT + 1) / 2 + TPB - 1) / TPB;

    k_gemm1_prep<<<GB1 + PB, 256>>>(x, W1, ei, as1, ad1);   // 0
    k_scan<<<NB1, SCAN_B>>>();                              // 1
    k_scatter<<<gScat, TPB>>>(ei);                          // 2
    k_l1<<<GW2, TPB>>>(b1);                                 // 3 <- profiled
    k_gemm2<<<(NNODES + 127) / 128, 256>>>(W2, as2, ad2);   // 4
    k_l2<<<GW2 + ZB2, TPB>>>(b2, out);                      // 5
}